// round 1
// baseline (speedup 1.0000x reference)
#include <cuda_runtime.h>
#include <cuda_bf16.h>
#include <cstdint>

#define Nn 8192
#define Dd 256
#define Kn 10

// ---------------- scratch (device globals: no allocation allowed) ----------
__device__ float g_Xsq[Nn];
__device__ float g_S[(size_t)Nn * (size_t)Nn];   // 256 MB: S[i][j] = Xsq[j] - 2*dot(Xi,Xj)
__device__ int   g_nbr[Nn * Kn];
__device__ float g_rowsum[Nn];

// ---------------- packed f32x2 helpers (FFMA2) -----------------------------
__device__ __forceinline__ uint64_t pack2(float a) {
    uint64_t p;
    unsigned int ai = __float_as_uint(a);
    asm("mov.b64 %0, {%1, %1};" : "=l"(p) : "r"(ai));
    return p;
}
__device__ __forceinline__ uint64_t ffma2(uint64_t a, uint64_t b, uint64_t c) {
    uint64_t d;
    asm("fma.rn.f32x2 %0, %1, %2, %3;" : "=l"(d) : "l"(a), "l"(b), "l"(c));
    return d;
}
__device__ __forceinline__ void unpack2(uint64_t v, float& lo, float& hi) {
    unsigned int l, h;
    asm("mov.b64 {%0, %1}, %2;" : "=r"(l), "=r"(h) : "l"(v));
    lo = __uint_as_float(l);
    hi = __uint_as_float(h);
}

// ---------------- kernel 1: row sums of squares ----------------------------
__global__ void xsq_kernel(const float* __restrict__ X) {
    int row  = blockIdx.x * 8 + (threadIdx.x >> 5);
    int lane = threadIdx.x & 31;
    const float4* xr = reinterpret_cast<const float4*>(X + (size_t)row * Dd);
    float4 u = xr[lane];
    float4 v = xr[lane + 32];
    float s = u.x*u.x + u.y*u.y + u.z*u.z + u.w*u.w
            + v.x*v.x + v.y*v.y + v.z*v.z + v.w*v.w;
    #pragma unroll
    for (int o = 16; o > 0; o >>= 1) s += __shfl_xor_sync(0xFFFFFFFFu, s, o);
    if (lane == 0) g_Xsq[row] = s;
}

// ---------------- kernel 2: tiled fp32 GEMM -> S ---------------------------
// 128x128 block tile, 8x8 per thread, BK=8, packed f32x2 accumulate.
__global__ void __launch_bounds__(256) gemm_kernel(const float* __restrict__ X) {
    __shared__ float As[8][132];   // padded to kill STS bank conflicts
    __shared__ float Bs[8][132];

    const int i0 = blockIdx.y * 128;
    const int j0 = blockIdx.x * 128;
    const int t  = threadIdx.x;
    const int tx = t & 15;         // 0..15  -> 8 cols each
    const int ty = t >> 4;         // 0..15  -> 8 rows each

    const int lr = t >> 1;          // 0..127 row within tile for loads
    const int lk = (t & 1) * 4;     // 0 or 4 k-offset for loads

    const float* Arow = X + (size_t)(i0 + lr) * Dd + lk;
    const float* Brow = X + (size_t)(j0 + lr) * Dd + lk;

    uint64_t acc[8][4];
    #pragma unroll
    for (int m = 0; m < 8; ++m)
        #pragma unroll
        for (int p = 0; p < 4; ++p) acc[m][p] = 0ull;

    for (int kt = 0; kt < Dd / 8; ++kt) {
        float4 fa = *reinterpret_cast<const float4*>(Arow + kt * 8);
        float4 fb = *reinterpret_cast<const float4*>(Brow + kt * 8);
        __syncthreads();
        As[lk + 0][lr] = fa.x; As[lk + 1][lr] = fa.y;
        As[lk + 2][lr] = fa.z; As[lk + 3][lr] = fa.w;
        Bs[lk + 0][lr] = fb.x; Bs[lk + 1][lr] = fb.y;
        Bs[lk + 2][lr] = fb.z; Bs[lk + 3][lr] = fb.w;
        __syncthreads();

        #pragma unroll
        for (int kk = 0; kk < 8; ++kk) {
            float4 a01 = *reinterpret_cast<const float4*>(&As[kk][ty * 8]);
            float4 a23 = *reinterpret_cast<const float4*>(&As[kk][ty * 8 + 4]);
            const uint64_t* bp = reinterpret_cast<const uint64_t*>(&Bs[kk][tx * 8]);
            uint64_t b0 = bp[0], b1 = bp[1], b2 = bp[2], b3 = bp[3];
            float av[8] = {a01.x, a01.y, a01.z, a01.w, a23.x, a23.y, a23.z, a23.w};
            #pragma unroll
            for (int m = 0; m < 8; ++m) {
                uint64_t am = pack2(av[m]);
                acc[m][0] = ffma2(am, b0, acc[m][0]);
                acc[m][1] = ffma2(am, b1, acc[m][1]);
                acc[m][2] = ffma2(am, b2, acc[m][2]);
                acc[m][3] = ffma2(am, b3, acc[m][3]);
            }
        }
    }

    float xs[8];
    #pragma unroll
    for (int n = 0; n < 8; ++n) xs[n] = g_Xsq[j0 + tx * 8 + n];

    #pragma unroll
    for (int m = 0; m < 8; ++m) {
        float o[8];
        #pragma unroll
        for (int p = 0; p < 4; ++p) {
            float lo, hi;
            unpack2(acc[m][p], lo, hi);
            o[2 * p]     = xs[2 * p]     - 2.0f * lo;
            o[2 * p + 1] = xs[2 * p + 1] - 2.0f * hi;
        }
        size_t base = (size_t)(i0 + ty * 8 + m) * Nn + (size_t)(j0 + tx * 8);
        *reinterpret_cast<float4*>(&g_S[base])     = make_float4(o[0], o[1], o[2], o[3]);
        *reinterpret_cast<float4*>(&g_S[base + 4]) = make_float4(o[4], o[5], o[6], o[7]);
    }
}

// ---------------- kernel 3: per-row top-10 (excluding self) ----------------
__global__ void __launch_bounds__(128) topk_kernel() {
    const int row = blockIdx.x;
    const int tid = threadIdx.x;

    float v[Kn];
    int   id[Kn];
    #pragma unroll
    for (int k = 0; k < Kn; ++k) { v[k] = 3.4e38f; id[k] = 0; }

    const float* Srow = g_S + (size_t)row * Nn;
    for (int j = tid; j < Nn; j += 128) {
        if (j == row) continue;
        float s = Srow[j];
        if (s < v[Kn - 1]) {
            int p = Kn - 1;
            #pragma unroll
            for (int q = 0; q < Kn - 1; ++q) {
                if (p > 0 && v[p - 1] > s) { v[p] = v[p - 1]; id[p] = id[p - 1]; --p; }
            }
            v[p] = s; id[p] = j;
        }
    }

    __shared__ float sv[128][Kn];
    __shared__ int   si[128][Kn];
    #pragma unroll
    for (int k = 0; k < Kn; ++k) { sv[tid][k] = v[k]; si[tid][k] = id[k]; }

    for (int step = 64; step >= 1; step >>= 1) {
        __syncthreads();
        if (tid < step) {
            float av[Kn]; int ai[Kn];
            #pragma unroll
            for (int k = 0; k < Kn; ++k) { av[k] = sv[tid][k]; ai[k] = si[tid][k]; }
            int ia = 0, ib = 0;
            float ov[Kn]; int oi[Kn];
            #pragma unroll
            for (int k = 0; k < Kn; ++k) {
                float bvv = sv[tid + step][ib];
                if (av[ia] <= bvv) { ov[k] = av[ia]; oi[k] = ai[ia]; ++ia; }
                else               { ov[k] = bvv;    oi[k] = si[tid + step][ib]; ++ib; }
            }
            #pragma unroll
            for (int k = 0; k < Kn; ++k) { sv[tid][k] = ov[k]; si[tid][k] = oi[k]; }
        }
    }
    __syncthreads();
    if (tid < Kn) g_nbr[row * Kn + tid] = si[0][tid];
}

// ---------------- kernel 4: per-row loss ----------------------------------
__global__ void __launch_bounds__(320) loss_kernel(const float* __restrict__ X,
                                                   const float* __restrict__ Z) {
    const int i = blockIdx.x;
    const int w = threadIdx.x >> 5;   // 0..9 neighbor
    const int l = threadIdx.x & 31;
    __shared__ float xd[Kn], zd[Kn];

    int nb = g_nbr[i * Kn + w];
    const float* xi = X + (size_t)i  * Dd;
    const float* xn = X + (size_t)nb * Dd;
    float sx = 0.0f;
    #pragma unroll
    for (int d = 0; d < Dd; d += 32) {
        float df = xi[d + l] - xn[d + l];
        sx = fmaf(df, df, sx);
    }
    const float* zi = Z + (size_t)i  * 64;
    const float* zn = Z + (size_t)nb * 64;
    float sz = 0.0f;
    #pragma unroll
    for (int d = 0; d < 64; d += 32) {
        float df = zi[d + l] - zn[d + l];
        sz = fmaf(df, df, sz);
    }
    #pragma unroll
    for (int o = 16; o > 0; o >>= 1) {
        sx += __shfl_xor_sync(0xFFFFFFFFu, sx, o);
        sz += __shfl_xor_sync(0xFFFFFFFFu, sz, o);
    }
    if (l == 0) { xd[w] = sqrtf(sx); zd[w] = sqrtf(sz); }
    __syncthreads();
    if (threadIdx.x == 0) {
        float xm = 0.0f, zm = 0.0f;
        #pragma unroll
        for (int k = 0; k < Kn; ++k) { xm = fmaxf(xm, xd[k]); zm = fmaxf(zm, zd[k]); }
        xm = fmaxf(xm, 1e-8f);
        zm = fmaxf(zm, 1e-8f);
        float s = 0.0f;
        #pragma unroll
        for (int k = 0; k < Kn; ++k) s += fabsf(xd[k] / xm - zd[k] / zm);
        g_rowsum[i] = s;
    }
}

// ---------------- kernel 5: deterministic final reduction ------------------
__global__ void __launch_bounds__(1024) reduce_kernel(float* __restrict__ out) {
    __shared__ float sm[1024];
    int t = threadIdx.x;
    float s = 0.0f;
    for (int i = t; i < Nn; i += 1024) s += g_rowsum[i];
    sm[t] = s;
    __syncthreads();
    for (int st = 512; st > 0; st >>= 1) {
        if (t < st) sm[t] += sm[t + st];
        __syncthreads();
    }
    if (t == 0) out[0] = sm[0] / (float)(Nn * Kn);
}

// ---------------- launch ---------------------------------------------------
extern "C" void kernel_launch(void* const* d_in, const int* in_sizes, int n_in,
                              void* d_out, int out_size) {
    const float* z = (const float*)d_in[0];
    const float* X = (const float*)d_in[1];
    if (n_in >= 2 && in_sizes[0] != Nn * 64) {  // robustness to input ordering
        z = (const float*)d_in[1];
        X = (const float*)d_in[0];
    }
    float* out = (float*)d_out;

    xsq_kernel<<<Nn / 8, 256>>>(X);
    dim3 g(Nn / 128, Nn / 128);
    gemm_kernel<<<g, 256>>>(X);
    topk_kernel<<<Nn, 128>>>();
    loss_kernel<<<Nn, 320>>>(X, z);
    reduce_kernel<<<1, 1024>>>(out);
}

// round 3
// speedup vs baseline: 1.2219x; 1.2219x over previous
#include <cuda_runtime.h>
#include <cuda_bf16.h>
#include <cstdint>

#define Nn 8192
#define Dd 256
#define Kn 10

// ---------------- scratch (device globals) ---------------------------------
__device__ float g_Xsq[Nn];
__device__ float g_S[(size_t)Nn * (size_t)Nn];   // S[i][j] = Xsq[j] - 2*dot(Xi,Xj)
__device__ int   g_nbr[Nn * Kn];
__device__ float g_rowsum[Nn];
__device__ uint4 g_Xhi4[Nn * Dd / 8];            // bf16 hi halves, 16B chunks
__device__ uint4 g_Xlo4[Nn * Dd / 8];            // bf16 lo halves

// ---------------- helpers --------------------------------------------------
__device__ __forceinline__ uint32_t smem_u32(const void* p) {
    uint32_t a;
    asm("{ .reg .u64 t; cvta.to.shared.u64 t, %1; cvt.u32.u64 %0, t; }" : "=r"(a) : "l"(p));
    return a;
}
__device__ __forceinline__ void cp16(uint32_t s, const void* g) {
    asm volatile("cp.async.cg.shared.global [%0], [%1], 16;" :: "r"(s), "l"(g));
}
#define CP_COMMIT() asm volatile("cp.async.commit_group;" ::: "memory")
#define CP_WAIT(n)  asm volatile("cp.async.wait_group %0;" :: "n"(n) : "memory")

__device__ __forceinline__ void ldsm_x4(uint32_t& r0, uint32_t& r1, uint32_t& r2, uint32_t& r3, uint32_t a) {
    asm volatile("ldmatrix.sync.aligned.m8n8.x4.shared.b16 {%0,%1,%2,%3}, [%4];"
                 : "=r"(r0), "=r"(r1), "=r"(r2), "=r"(r3) : "r"(a));
}
__device__ __forceinline__ void ldsm_x2(uint32_t& r0, uint32_t& r1, uint32_t a) {
    asm volatile("ldmatrix.sync.aligned.m8n8.x2.shared.b16 {%0,%1}, [%2];"
                 : "=r"(r0), "=r"(r1) : "r"(a));
}
__device__ __forceinline__ void mma16816(float* d, const uint32_t* a, const uint32_t* b) {
    asm volatile("mma.sync.aligned.m16n8k16.row.col.f32.bf16.bf16.f32 "
                 "{%0,%1,%2,%3}, {%4,%5,%6,%7}, {%8,%9}, {%0,%1,%2,%3};"
                 : "+f"(d[0]), "+f"(d[1]), "+f"(d[2]), "+f"(d[3])
                 : "r"(a[0]), "r"(a[1]), "r"(a[2]), "r"(a[3]), "r"(b[0]), "r"(b[1]));
}

// ---------------- kernel 0: fp32 -> bf16 hi/lo split -----------------------
__global__ void convert_kernel(const float* __restrict__ X) {
    int i = blockIdx.x * 256 + threadIdx.x;           // one uint4 (8 bf16) each
    const float4* xp = reinterpret_cast<const float4*>(X) + i * 2;
    float4 a = xp[0], b = xp[1];
    float v[8] = {a.x, a.y, a.z, a.w, b.x, b.y, b.z, b.w};
    __nv_bfloat16 hi[8], lo[8];
    #pragma unroll
    for (int k = 0; k < 8; ++k) {
        hi[k] = __float2bfloat16(v[k]);
        lo[k] = __float2bfloat16(v[k] - __bfloat162float(hi[k]));
    }
    g_Xhi4[i] = *reinterpret_cast<uint4*>(hi);
    g_Xlo4[i] = *reinterpret_cast<uint4*>(lo);
}

// ---------------- kernel 1: row sums of squares ----------------------------
__global__ void xsq_kernel(const float* __restrict__ X) {
    int row  = blockIdx.x * 8 + (threadIdx.x >> 5);
    int lane = threadIdx.x & 31;
    const float4* xr = reinterpret_cast<const float4*>(X + (size_t)row * Dd);
    float4 u = xr[lane];
    float4 v = xr[lane + 32];
    float s = u.x*u.x + u.y*u.y + u.z*u.z + u.w*u.w
            + v.x*v.x + v.y*v.y + v.z*v.z + v.w*v.w;
    #pragma unroll
    for (int o = 16; o > 0; o >>= 1) s += __shfl_xor_sync(0xFFFFFFFFu, s, o);
    if (lane == 0) g_Xsq[row] = s;
}

// ---------------- kernel 2: bf16-split HMMA GEMM -> S ----------------------
// CTA 128x128, 8 warps each 64x32, BK=32, double-buffered cp.async.
#define BKc     32
#define NCHUNK  (Dd / BKc)            // 8
#define STRIDE  40                    // bf16 elems per smem row (80B, padded)
#define TILE_B  (128 * STRIDE * 2)    // 10240 B
#define STAGE_B (4 * TILE_B)          // Ahi, Alo, Bhi, Blo
#define SMEM_DYN (2 * STAGE_B)        // 81920 B

__global__ void __launch_bounds__(256) gemm_mma_kernel() {
    extern __shared__ char dynsm[];
    const uint32_t smb = smem_u32(dynsm);

    const int t = threadIdx.x, wid = t >> 5, lane = t & 31;
    const int i0 = blockIdx.y * 128, j0 = blockIdx.x * 128;
    const int warpM = wid & 1, warpN = wid >> 1;       // 2 x 4 warp grid

    // ---- load mapping: 2 threads per row, 2x16B each, per tile ----
    const int lrow = t >> 1, lh = t & 1;
    const uint4* gAhi = g_Xhi4 + (size_t)(i0 + lrow) * 32;
    const uint4* gAlo = g_Xlo4 + (size_t)(i0 + lrow) * 32;
    const uint4* gBhi = g_Xhi4 + (size_t)(j0 + lrow) * 32;
    const uint4* gBlo = g_Xlo4 + (size_t)(j0 + lrow) * 32;

    float acc[4][4][4];
    #pragma unroll
    for (int mt = 0; mt < 4; ++mt)
        #pragma unroll
        for (int nt = 0; nt < 4; ++nt)
            #pragma unroll
            for (int q = 0; q < 4; ++q) acc[mt][nt][q] = 0.0f;

    // ---- ldmatrix base addresses for this thread ----
    // A frags: row = mbase + (lane&15), kbyteoff = (lane>>4)*16
    const int arow = (lane & 15), akoff = (lane >> 4) * 16;  // bytes
    // B frags: row = nbase + (lane&7), kbyteoff = ((lane>>3)&1)*16
    const int brow = (lane & 7),  bkoff = ((lane >> 3) & 1) * 16;

    auto issue_stage = [&](int c, int b) {
        uint32_t st = smb + b * STAGE_B;
        #pragma unroll
        for (int q = 0; q < 2; ++q) {
            int idx = lh * 2 + q;                       // uint4 within 64B row chunk
            uint32_t off = (uint32_t)(lrow * 80 + idx * 16);
            int go = c * 4 + idx;
            cp16(st + 0 * TILE_B + off, gAhi + go);
            cp16(st + 1 * TILE_B + off, gAlo + go);
            cp16(st + 2 * TILE_B + off, gBhi + go);
            cp16(st + 3 * TILE_B + off, gBlo + go);
        }
        CP_COMMIT();
    };

    issue_stage(0, 0);

    for (int c = 0; c < NCHUNK; ++c) {
        const int b = c & 1;
        if (c + 1 < NCHUNK) {
            issue_stage(c + 1, (c + 1) & 1);
            CP_WAIT(1);
        } else {
            CP_WAIT(0);
        }
        __syncthreads();

        const uint32_t st = smb + b * STAGE_B;
        #pragma unroll
        for (int ks = 0; ks < 2; ++ks) {
            const int kb = ks * 32;                     // byte offset of k-step (16 elems)
            uint32_t Ahi[4][4], Alo[4][4], Bhi[4][2], Blo[4][2];
            #pragma unroll
            for (int mt = 0; mt < 4; ++mt) {
                uint32_t a = st + (uint32_t)((warpM * 64 + mt * 16 + arow) * 80 + kb + akoff);
                ldsm_x4(Ahi[mt][0], Ahi[mt][1], Ahi[mt][2], Ahi[mt][3], a + 0 * TILE_B);
                ldsm_x4(Alo[mt][0], Alo[mt][1], Alo[mt][2], Alo[mt][3], a + 1 * TILE_B);
            }
            #pragma unroll
            for (int nt = 0; nt < 4; ++nt) {
                uint32_t a = st + (uint32_t)((warpN * 32 + nt * 8 + brow) * 80 + kb + bkoff);
                ldsm_x2(Bhi[nt][0], Bhi[nt][1], a + 2 * TILE_B);
                ldsm_x2(Blo[nt][0], Blo[nt][1], a + 3 * TILE_B);
            }
            #pragma unroll
            for (int mt = 0; mt < 4; ++mt)
                #pragma unroll
                for (int nt = 0; nt < 4; ++nt) {
                    mma16816(acc[mt][nt], Ahi[mt], Bhi[nt]);
                    mma16816(acc[mt][nt], Ahi[mt], Blo[nt]);
                    mma16816(acc[mt][nt], Alo[mt], Bhi[nt]);
                }
        }
        __syncthreads();
    }

    // ---- epilogue: S[i][j] = Xsq[j] - 2*acc ----
    const int gq = lane >> 2, tig = lane & 3;
    #pragma unroll
    for (int nt = 0; nt < 4; ++nt) {
        const int col = j0 + warpN * 32 + nt * 8 + tig * 2;
        const float2 xs = *reinterpret_cast<const float2*>(&g_Xsq[col]);
        #pragma unroll
        for (int mt = 0; mt < 4; ++mt) {
            const int r0 = i0 + warpM * 64 + mt * 16 + gq;
            float* d = acc[mt][nt];
            *reinterpret_cast<float2*>(&g_S[(size_t)r0 * Nn + col]) =
                make_float2(xs.x - 2.0f * d[0], xs.y - 2.0f * d[1]);
            *reinterpret_cast<float2*>(&g_S[(size_t)(r0 + 8) * Nn + col]) =
                make_float2(xs.x - 2.0f * d[2], xs.y - 2.0f * d[3]);
        }
    }
}

// ---------------- kernel 3: per-row top-10 (excluding self) ----------------
__global__ void __launch_bounds__(128) topk_kernel() {
    const int row = blockIdx.x;
    const int tid = threadIdx.x;

    float v[Kn];
    int   id[Kn];
    #pragma unroll
    for (int k = 0; k < Kn; ++k) { v[k] = 3.4e38f; id[k] = 0; }

    const float* Srow = g_S + (size_t)row * Nn;
    for (int j = tid; j < Nn; j += 128) {
        if (j == row) continue;
        float s = Srow[j];
        if (s < v[Kn - 1]) {
            int p = Kn - 1;
            #pragma unroll
            for (int q = 0; q < Kn - 1; ++q) {
                if (p > 0 && v[p - 1] > s) { v[p] = v[p - 1]; id[p] = id[p - 1]; --p; }
            }
            v[p] = s; id[p] = j;
        }
    }

    __shared__ float sv[128][Kn];
    __shared__ int   si[128][Kn];
    #pragma unroll
    for (int k = 0; k < Kn; ++k) { sv[tid][k] = v[k]; si[tid][k] = id[k]; }

    for (int step = 64; step >= 1; step >>= 1) {
        __syncthreads();
        if (tid < step) {
            float av[Kn]; int ai[Kn];
            #pragma unroll
            for (int k = 0; k < Kn; ++k) { av[k] = sv[tid][k]; ai[k] = si[tid][k]; }
            int ia = 0, ib = 0;
            float ov[Kn]; int oi[Kn];
            #pragma unroll
            for (int k = 0; k < Kn; ++k) {
                float bvv = sv[tid + step][ib];
                if (av[ia] <= bvv) { ov[k] = av[ia]; oi[k] = ai[ia]; ++ia; }
                else               { ov[k] = bvv;    oi[k] = si[tid + step][ib]; ++ib; }
            }
            #pragma unroll
            for (int k = 0; k < Kn; ++k) { sv[tid][k] = ov[k]; si[tid][k] = oi[k]; }
        }
    }
    __syncthreads();
    if (tid < Kn) g_nbr[row * Kn + tid] = si[0][tid];
}

// ---------------- kernel 4: per-row loss ----------------------------------
__global__ void __launch_bounds__(320) loss_kernel(const float* __restrict__ X,
                                                   const float* __restrict__ Z) {
    const int i = blockIdx.x;
    const int w = threadIdx.x >> 5;   // 0..9 neighbor
    const int l = threadIdx.x & 31;
    __shared__ float xd[Kn], zd[Kn];

    int nb = g_nbr[i * Kn + w];
    const float* xi = X + (size_t)i  * Dd;
    const float* xn = X + (size_t)nb * Dd;
    float sx = 0.0f;
    #pragma unroll
    for (int d = 0; d < Dd; d += 32) {
        float df = xi[d + l] - xn[d + l];
        sx = fmaf(df, df, sx);
    }
    const float* zi = Z + (size_t)i  * 64;
    const float* zn = Z + (size_t)nb * 64;
    float sz = 0.0f;
    #pragma unroll
    for (int d = 0; d < 64; d += 32) {
        float df = zi[d + l] - zn[d + l];
        sz = fmaf(df, df, sz);
    }
    #pragma unroll
    for (int o = 16; o > 0; o >>= 1) {
        sx += __shfl_xor_sync(0xFFFFFFFFu, sx, o);
        sz += __shfl_xor_sync(0xFFFFFFFFu, sz, o);
    }
    if (l == 0) { xd[w] = sqrtf(sx); zd[w] = sqrtf(sz); }
    __syncthreads();
    if (threadIdx.x == 0) {
        float xm = 0.0f, zm = 0.0f;
        #pragma unroll
        for (int k = 0; k < Kn; ++k) { xm = fmaxf(xm, xd[k]); zm = fmaxf(zm, zd[k]); }
        xm = fmaxf(xm, 1e-8f);
        zm = fmaxf(zm, 1e-8f);
        float s = 0.0f;
        #pragma unroll
        for (int k = 0; k < Kn; ++k) s += fabsf(xd[k] / xm - zd[k] / zm);
        g_rowsum[i] = s;
    }
}

// ---------------- kernel 5: deterministic final reduction ------------------
__global__ void __launch_bounds__(1024) reduce_kernel(float* __restrict__ out) {
    __shared__ float sm[1024];
    int t = threadIdx.x;
    float s = 0.0f;
    for (int i = t; i < Nn; i += 1024) s += g_rowsum[i];
    sm[t] = s;
    __syncthreads();
    for (int st = 512; st > 0; st >>= 1) {
        if (t < st) sm[t] += sm[t + st];
        __syncthreads();
    }
    if (t == 0) out[0] = sm[0] / (float)(Nn * Kn);
}

// ---------------- launch ---------------------------------------------------
extern "C" void kernel_launch(void* const* d_in, const int* in_sizes, int n_in,
                              void* d_out, int out_size) {
    const float* z = (const float*)d_in[0];
    const float* X = (const float*)d_in[1];
    if (n_in >= 2 && in_sizes[0] != Nn * 64) {
        z = (const float*)d_in[1];
        X = (const float*)d_in[0];
    }
    float* out = (float*)d_out;

    cudaFuncSetAttribute(gemm_mma_kernel, cudaFuncAttributeMaxDynamicSharedMemorySize, SMEM_DYN);

    convert_kernel<<<Nn * Dd / 8 / 256, 256>>>(X);
    xsq_kernel<<<Nn / 8, 256>>>(X);
    dim3 g(Nn / 128, Nn / 128);
    gemm_mma_kernel<<<g, 256, SMEM_DYN>>>();
    topk_kernel<<<Nn, 128>>>();
    loss_kernel<<<Nn, 320>>>(X, z);
    reduce_kernel<<<1, 1024>>>(out);
}

// round 4
// speedup vs baseline: 1.3490x; 1.1040x over previous
#include <cuda_runtime.h>
#include <cuda_bf16.h>
#include <cstdint>

#define Nn 8192
#define Dd 256
#define Kn 10

// ---------------- scratch (device globals) ---------------------------------
__device__ float g_Xsq[Nn];
__device__ float g_S[(size_t)Nn * (size_t)Nn];   // S[i][j] = Xsq[j] - 2*dot(Xi,Xj)
__device__ int   g_nbr[Nn * Kn];
__device__ float g_rowsum[Nn];
__device__ uint4 g_Xhi4[Nn * Dd / 8];            // bf16 hi halves, 16B chunks
__device__ uint4 g_Xlo4[Nn * Dd / 8];            // bf16 lo halves

// ---------------- helpers --------------------------------------------------
__device__ __forceinline__ uint32_t smem_u32(const void* p) {
    uint32_t a;
    asm("{ .reg .u64 t; cvta.to.shared.u64 t, %1; cvt.u32.u64 %0, t; }" : "=r"(a) : "l"(p));
    return a;
}
__device__ __forceinline__ void cp16(uint32_t s, const void* g) {
    asm volatile("cp.async.cg.shared.global [%0], [%1], 16;" :: "r"(s), "l"(g));
}
#define CP_COMMIT() asm volatile("cp.async.commit_group;" ::: "memory")
#define CP_WAIT(n)  asm volatile("cp.async.wait_group %0;" :: "n"(n) : "memory")

__device__ __forceinline__ void ldsm_x4(uint32_t& r0, uint32_t& r1, uint32_t& r2, uint32_t& r3, uint32_t a) {
    asm volatile("ldmatrix.sync.aligned.m8n8.x4.shared.b16 {%0,%1,%2,%3}, [%4];"
                 : "=r"(r0), "=r"(r1), "=r"(r2), "=r"(r3) : "r"(a));
}
__device__ __forceinline__ void ldsm_x2(uint32_t& r0, uint32_t& r1, uint32_t a) {
    asm volatile("ldmatrix.sync.aligned.m8n8.x2.shared.b16 {%0,%1}, [%2];"
                 : "=r"(r0), "=r"(r1) : "r"(a));
}
__device__ __forceinline__ void mma16816(float* d, const uint32_t* a, const uint32_t* b) {
    asm volatile("mma.sync.aligned.m16n8k16.row.col.f32.bf16.bf16.f32 "
                 "{%0,%1,%2,%3}, {%4,%5,%6,%7}, {%8,%9}, {%0,%1,%2,%3};"
                 : "+f"(d[0]), "+f"(d[1]), "+f"(d[2]), "+f"(d[3])
                 : "r"(a[0]), "r"(a[1]), "r"(a[2]), "r"(a[3]), "r"(b[0]), "r"(b[1]));
}

// ---------------- kernel 0: fp32 -> bf16 hi/lo split -----------------------
__global__ void convert_kernel(const float* __restrict__ X) {
    int i = blockIdx.x * 256 + threadIdx.x;           // one uint4 (8 bf16) each
    const float4* xp = reinterpret_cast<const float4*>(X) + i * 2;
    float4 a = xp[0], b = xp[1];
    float v[8] = {a.x, a.y, a.z, a.w, b.x, b.y, b.z, b.w};
    __nv_bfloat16 hi[8], lo[8];
    #pragma unroll
    for (int k = 0; k < 8; ++k) {
        hi[k] = __float2bfloat16(v[k]);
        lo[k] = __float2bfloat16(v[k] - __bfloat162float(hi[k]));
    }
    g_Xhi4[i] = *reinterpret_cast<uint4*>(hi);
    g_Xlo4[i] = *reinterpret_cast<uint4*>(lo);
}

// ---------------- kernel 1: row sums of squares ----------------------------
__global__ void xsq_kernel(const float* __restrict__ X) {
    int row  = blockIdx.x * 8 + (threadIdx.x >> 5);
    int lane = threadIdx.x & 31;
    const float4* xr = reinterpret_cast<const float4*>(X + (size_t)row * Dd);
    float4 u = xr[lane];
    float4 v = xr[lane + 32];
    float s = u.x*u.x + u.y*u.y + u.z*u.z + u.w*u.w
            + v.x*v.x + v.y*v.y + v.z*v.z + v.w*v.w;
    #pragma unroll
    for (int o = 16; o > 0; o >>= 1) s += __shfl_xor_sync(0xFFFFFFFFu, s, o);
    if (lane == 0) g_Xsq[row] = s;
}

// ---------------- kernel 2: symmetric bf16-split HMMA GEMM -> S ------------
// Lower-triangular 128x128 tiles only (2080 CTAs); mirror-write transpose.
// 8 warps each 64x32, BK=32, double-buffered cp.async, smem-staged epilogue.
#define BKc     32
#define NCHUNK  (Dd / BKc)            // 8
#define TILE_B  (128 * 80)            // 10240 B (80B padded rows)
#define STAGE_B (4 * TILE_B)          // Ahi, Alo, Bhi, Blo
#define SMEM_DYN (2 * STAGE_B)        // 81920 B (>= 128*129*4 epilogue stage)

__global__ void __launch_bounds__(256, 2) gemm_mma_kernel() {
    extern __shared__ char dynsm[];
    const uint32_t smb = smem_u32(dynsm);

    const int t = threadIdx.x, wid = t >> 5, lane = t & 31;

    // triangular decode: blockIdx.x -> (bi, bj), bi >= bj
    int tidx = blockIdx.x;
    int bi = (int)((-1.0f + sqrtf(1.0f + 8.0f * (float)tidx)) * 0.5f);
    while ((bi + 1) * (bi + 2) / 2 <= tidx) ++bi;
    while (bi * (bi + 1) / 2 > tidx) --bi;
    int bj = tidx - bi * (bi + 1) / 2;
    const int i0 = bi * 128, j0 = bj * 128;

    const int warpM = wid & 1, warpN = wid >> 1;       // 2 x 4 warp grid

    // ---- load mapping: 2 threads per row, 2x16B each, per tile ----
    const int lrow = t >> 1, lh = t & 1;
    const uint4* gAhi = g_Xhi4 + (size_t)(i0 + lrow) * 32;
    const uint4* gAlo = g_Xlo4 + (size_t)(i0 + lrow) * 32;
    const uint4* gBhi = g_Xhi4 + (size_t)(j0 + lrow) * 32;
    const uint4* gBlo = g_Xlo4 + (size_t)(j0 + lrow) * 32;

    float acc[4][4][4];
    #pragma unroll
    for (int mt = 0; mt < 4; ++mt)
        #pragma unroll
        for (int nt = 0; nt < 4; ++nt)
            #pragma unroll
            for (int q = 0; q < 4; ++q) acc[mt][nt][q] = 0.0f;

    const int arow = (lane & 15), akoff = (lane >> 4) * 16;
    const int brow = (lane & 7),  bkoff = ((lane >> 3) & 1) * 16;

    auto issue_stage = [&](int c, int b) {
        uint32_t st = smb + b * STAGE_B;
        #pragma unroll
        for (int q = 0; q < 2; ++q) {
            int idx = lh * 2 + q;
            uint32_t off = (uint32_t)(lrow * 80 + idx * 16);
            int go = c * 4 + idx;
            cp16(st + 0 * TILE_B + off, gAhi + go);
            cp16(st + 1 * TILE_B + off, gAlo + go);
            cp16(st + 2 * TILE_B + off, gBhi + go);
            cp16(st + 3 * TILE_B + off, gBlo + go);
        }
        CP_COMMIT();
    };

    issue_stage(0, 0);

    for (int c = 0; c < NCHUNK; ++c) {
        const int b = c & 1;
        if (c + 1 < NCHUNK) {
            issue_stage(c + 1, (c + 1) & 1);
            CP_WAIT(1);
        } else {
            CP_WAIT(0);
        }
        __syncthreads();

        const uint32_t st = smb + b * STAGE_B;
        #pragma unroll
        for (int ks = 0; ks < 2; ++ks) {
            const int kb = ks * 32;
            uint32_t Ahi[4][4], Alo[4][4];
            #pragma unroll
            for (int mt = 0; mt < 4; ++mt) {
                uint32_t a = st + (uint32_t)((warpM * 64 + mt * 16 + arow) * 80 + kb + akoff);
                ldsm_x4(Ahi[mt][0], Ahi[mt][1], Ahi[mt][2], Ahi[mt][3], a + 0 * TILE_B);
                ldsm_x4(Alo[mt][0], Alo[mt][1], Alo[mt][2], Alo[mt][3], a + 1 * TILE_B);
            }
            #pragma unroll
            for (int nt = 0; nt < 4; ++nt) {
                uint32_t ba = st + (uint32_t)((warpN * 32 + nt * 8 + brow) * 80 + kb + bkoff);
                uint32_t Bhi[2], Blo[2];
                ldsm_x2(Bhi[0], Bhi[1], ba + 2 * TILE_B);
                ldsm_x2(Blo[0], Blo[1], ba + 3 * TILE_B);
                #pragma unroll
                for (int mt = 0; mt < 4; ++mt) {
                    mma16816(acc[mt][nt], Ahi[mt], Bhi);
                    mma16816(acc[mt][nt], Alo[mt], Bhi);
                    mma16816(acc[mt][nt], Ahi[mt], Blo);
                }
            }
        }
        __syncthreads();
    }

    // ---- epilogue: stage dot tile in smem, coalesced writes ----
    float* stg = reinterpret_cast<float*>(dynsm);      // 128 x 129 floats
    const int gq = lane >> 2, tig = lane & 3;
    #pragma unroll
    for (int nt = 0; nt < 4; ++nt) {
        const int col = warpN * 32 + nt * 8 + tig * 2;
        #pragma unroll
        for (int mt = 0; mt < 4; ++mt) {
            const int r0 = warpM * 64 + mt * 16 + gq;
            float* d = acc[mt][nt];
            stg[r0 * 129 + col]           = d[0];
            stg[r0 * 129 + col + 1]       = d[1];
            stg[(r0 + 8) * 129 + col]     = d[2];
            stg[(r0 + 8) * 129 + col + 1] = d[3];
        }
    }
    __syncthreads();

    // normal tile: row i0+r, cols j0 + lane*4 .. +3
    for (int r = wid; r < 128; r += 8) {
        const int cc = lane * 4;
        const float4 xs = *reinterpret_cast<const float4*>(&g_Xsq[j0 + cc]);
        const float* sr = &stg[r * 129 + cc];
        float4 o = make_float4(xs.x - 2.0f * sr[0], xs.y - 2.0f * sr[1],
                               xs.z - 2.0f * sr[2], xs.w - 2.0f * sr[3]);
        *reinterpret_cast<float4*>(&g_S[(size_t)(i0 + r) * Nn + j0 + cc]) = o;
    }
    // transposed tile (off-diagonal only): row j0+r, cols i0 + lane*4 .. +3
    if (bi != bj) {
        for (int r = wid; r < 128; r += 8) {
            const int cc = lane * 4;
            const float4 xs = *reinterpret_cast<const float4*>(&g_Xsq[i0 + cc]);
            float4 o = make_float4(xs.x - 2.0f * stg[(cc + 0) * 129 + r],
                                   xs.y - 2.0f * stg[(cc + 1) * 129 + r],
                                   xs.z - 2.0f * stg[(cc + 2) * 129 + r],
                                   xs.w - 2.0f * stg[(cc + 3) * 129 + r]);
            *reinterpret_cast<float4*>(&g_S[(size_t)(j0 + r) * Nn + i0 + cc]) = o;
        }
    }
}

// ---------------- kernel 3: per-row top-10 (excluding self) ----------------
__global__ void __launch_bounds__(128) topk_kernel() {
    const int row = blockIdx.x;
    const int tid = threadIdx.x;

    float v[Kn];
    int   id[Kn];
    #pragma unroll
    for (int k = 0; k < Kn; ++k) { v[k] = 3.4e38f; id[k] = 0; }

    const float* Srow = g_S + (size_t)row * Nn;
    for (int j = tid; j < Nn; j += 128) {
        if (j == row) continue;
        float s = Srow[j];
        if (s < v[Kn - 1]) {
            int p = Kn - 1;
            #pragma unroll
            for (int q = 0; q < Kn - 1; ++q) {
                if (p > 0 && v[p - 1] > s) { v[p] = v[p - 1]; id[p] = id[p - 1]; --p; }
            }
            v[p] = s; id[p] = j;
        }
    }

    __shared__ float sv[128][Kn];
    __shared__ int   si[128][Kn];
    #pragma unroll
    for (int k = 0; k < Kn; ++k) { sv[tid][k] = v[k]; si[tid][k] = id[k]; }

    for (int step = 64; step >= 1; step >>= 1) {
        __syncthreads();
        if (tid < step) {
            float av[Kn]; int ai[Kn];
            #pragma unroll
            for (int k = 0; k < Kn; ++k) { av[k] = sv[tid][k]; ai[k] = si[tid][k]; }
            int ia = 0, ib = 0;
            float ov[Kn]; int oi[Kn];
            #pragma unroll
            for (int k = 0; k < Kn; ++k) {
                float bvv = sv[tid + step][ib];
                if (av[ia] <= bvv) { ov[k] = av[ia]; oi[k] = ai[ia]; ++ia; }
                else               { ov[k] = bvv;    oi[k] = si[tid + step][ib]; ++ib; }
            }
            #pragma unroll
            for (int k = 0; k < Kn; ++k) { sv[tid][k] = ov[k]; si[tid][k] = oi[k]; }
        }
    }
    __syncthreads();
    if (tid < Kn) g_nbr[row * Kn + tid] = si[0][tid];
}

// ---------------- kernel 4: per-row loss ----------------------------------
__global__ void __launch_bounds__(320) loss_kernel(const float* __restrict__ X,
                                                   const float* __restrict__ Z) {
    const int i = blockIdx.x;
    const int w = threadIdx.x >> 5;   // 0..9 neighbor
    const int l = threadIdx.x & 31;
    __shared__ float xd[Kn], zd[Kn];

    int nb = g_nbr[i * Kn + w];
    const float* xi = X + (size_t)i  * Dd;
    const float* xn = X + (size_t)nb * Dd;
    float sx = 0.0f;
    #pragma unroll
    for (int d = 0; d < Dd; d += 32) {
        float df = xi[d + l] - xn[d + l];
        sx = fmaf(df, df, sx);
    }
    const float* zi = Z + (size_t)i  * 64;
    const float* zn = Z + (size_t)nb * 64;
    float sz = 0.0f;
    #pragma unroll
    for (int d = 0; d < 64; d += 32) {
        float df = zi[d + l] - zn[d + l];
        sz = fmaf(df, df, sz);
    }
    #pragma unroll
    for (int o = 16; o > 0; o >>= 1) {
        sx += __shfl_xor_sync(0xFFFFFFFFu, sx, o);
        sz += __shfl_xor_sync(0xFFFFFFFFu, sz, o);
    }
    if (l == 0) { xd[w] = sqrtf(sx); zd[w] = sqrtf(sz); }
    __syncthreads();
    if (threadIdx.x == 0) {
        float xm = 0.0f, zm = 0.0f;
        #pragma unroll
        for (int k = 0; k < Kn; ++k) { xm = fmaxf(xm, xd[k]); zm = fmaxf(zm, zd[k]); }
        xm = fmaxf(xm, 1e-8f);
        zm = fmaxf(zm, 1e-8f);
        float s = 0.0f;
        #pragma unroll
        for (int k = 0; k < Kn; ++k) s += fabsf(xd[k] / xm - zd[k] / zm);
        g_rowsum[i] = s;
    }
}

// ---------------- kernel 5: deterministic final reduction ------------------
__global__ void __launch_bounds__(1024) reduce_kernel(float* __restrict__ out) {
    __shared__ float sm[1024];
    int t = threadIdx.x;
    float s = 0.0f;
    for (int i = t; i < Nn; i += 1024) s += g_rowsum[i];
    sm[t] = s;
    __syncthreads();
    for (int st = 512; st > 0; st >>= 1) {
        if (t < st) sm[t] += sm[t + st];
        __syncthreads();
    }
    if (t == 0) out[0] = sm[0] / (float)(Nn * Kn);
}

// ---------------- launch ---------------------------------------------------
extern "C" void kernel_launch(void* const* d_in, const int* in_sizes, int n_in,
                              void* d_out, int out_size) {
    const float* z = (const float*)d_in[0];
    const float* X = (const float*)d_in[1];
    if (n_in >= 2 && in_sizes[0] != Nn * 64) {
        z = (const float*)d_in[1];
        X = (const float*)d_in[0];
    }
    float* out = (float*)d_out;

    cudaFuncSetAttribute(gemm_mma_kernel, cudaFuncAttributeMaxDynamicSharedMemorySize, SMEM_DYN);

    convert_kernel<<<Nn * Dd / 8 / 256, 256>>>(X);
    xsq_kernel<<<Nn / 8, 256>>>(X);
    gemm_mma_kernel<<<64 * 65 / 2, 256, SMEM_DYN>>>();
    topk_kernel<<<Nn, 128>>>();
    loss_kernel<<<Nn, 320>>>(X, z);
    reduce_kernel<<<1, 1024>>>(out);
}

// round 5
// speedup vs baseline: 5.3860x; 3.9927x over previous
#include <cuda_runtime.h>
#include <cuda_bf16.h>
#include <cstdint>

#define Nn 8192
#define Dd 256
#define Kn 10
#define NTILE 64                      // Nn / 128

// ---------------- scratch (device globals) ---------------------------------
__device__ float g_Xsq[Nn];
__device__ float2 g_cand[(size_t)Nn * NTILE * Kn];   // 42 MB: per (row, coltile) sorted top-10
__device__ int   g_nbr[Nn * Kn];
__device__ float g_rowsum[Nn];
__device__ uint4 g_Xhi4[Nn * Dd / 8];
__device__ uint4 g_Xlo4[Nn * Dd / 8];

// ---------------- helpers --------------------------------------------------
__device__ __forceinline__ uint32_t smem_u32(const void* p) {
    uint32_t a;
    asm("{ .reg .u64 t; cvta.to.shared.u64 t, %1; cvt.u32.u64 %0, t; }" : "=r"(a) : "l"(p));
    return a;
}
__device__ __forceinline__ void cp16(uint32_t s, const void* g) {
    asm volatile("cp.async.cg.shared.global [%0], [%1], 16;" :: "r"(s), "l"(g));
}
#define CP_COMMIT() asm volatile("cp.async.commit_group;" ::: "memory")
#define CP_WAIT(n)  asm volatile("cp.async.wait_group %0;" :: "n"(n) : "memory")

__device__ __forceinline__ void ldsm_x4(uint32_t& r0, uint32_t& r1, uint32_t& r2, uint32_t& r3, uint32_t a) {
    asm volatile("ldmatrix.sync.aligned.m8n8.x4.shared.b16 {%0,%1,%2,%3}, [%4];"
                 : "=r"(r0), "=r"(r1), "=r"(r2), "=r"(r3) : "r"(a));
}
__device__ __forceinline__ void ldsm_x2(uint32_t& r0, uint32_t& r1, uint32_t a) {
    asm volatile("ldmatrix.sync.aligned.m8n8.x2.shared.b16 {%0,%1}, [%2];"
                 : "=r"(r0), "=r"(r1) : "r"(a));
}
__device__ __forceinline__ void mma16816(float* d, const uint32_t* a, const uint32_t* b) {
    asm volatile("mma.sync.aligned.m16n8k16.row.col.f32.bf16.bf16.f32 "
                 "{%0,%1,%2,%3}, {%4,%5,%6,%7}, {%8,%9}, {%0,%1,%2,%3};"
                 : "+f"(d[0]), "+f"(d[1]), "+f"(d[2]), "+f"(d[3])
                 : "r"(a[0]), "r"(a[1]), "r"(a[2]), "r"(a[3]), "r"(b[0]), "r"(b[1]));
}

// register-resident sorted-10 insert (static indices only -> no local mem)
#define TOP10_INSERT(s, j, v, id)                                              \
    if ((s) < v[9]) {                                                          \
        v[9] = (s); id[9] = (j);                                               \
        _Pragma("unroll")                                                      \
        for (int _k = 8; _k >= 0; --_k) {                                      \
            if (v[_k + 1] < v[_k]) {                                           \
                float _tv = v[_k]; v[_k] = v[_k + 1]; v[_k + 1] = _tv;         \
                int _ti = id[_k]; id[_k] = id[_k + 1]; id[_k + 1] = _ti;       \
            }                                                                  \
        }                                                                      \
    }

// ---------------- kernel 0: fp32 -> bf16 hi/lo split -----------------------
__global__ void convert_kernel(const float* __restrict__ X) {
    int i = blockIdx.x * 256 + threadIdx.x;
    const float4* xp = reinterpret_cast<const float4*>(X) + i * 2;
    float4 a = xp[0], b = xp[1];
    float v[8] = {a.x, a.y, a.z, a.w, b.x, b.y, b.z, b.w};
    __nv_bfloat16 hi[8], lo[8];
    #pragma unroll
    for (int k = 0; k < 8; ++k) {
        hi[k] = __float2bfloat16(v[k]);
        lo[k] = __float2bfloat16(v[k] - __bfloat162float(hi[k]));
    }
    g_Xhi4[i] = *reinterpret_cast<uint4*>(hi);
    g_Xlo4[i] = *reinterpret_cast<uint4*>(lo);
}

// ---------------- kernel 1: row sums of squares ----------------------------
__global__ void xsq_kernel(const float* __restrict__ X) {
    int row  = blockIdx.x * 8 + (threadIdx.x >> 5);
    int lane = threadIdx.x & 31;
    const float4* xr = reinterpret_cast<const float4*>(X + (size_t)row * Dd);
    float4 u = xr[lane];
    float4 v = xr[lane + 32];
    float s = u.x*u.x + u.y*u.y + u.z*u.z + u.w*u.w
            + v.x*v.x + v.y*v.y + v.z*v.z + v.w*v.w;
    #pragma unroll
    for (int o = 16; o > 0; o >>= 1) s += __shfl_xor_sync(0xFFFFFFFFu, s, o);
    if (lane == 0) g_Xsq[row] = s;
}

// ---------------- kernel 2: symmetric HMMA GEMM + fused per-tile top-10 ----
#define BKc     32
#define NCHUNK  (Dd / BKc)            // 8
#define TILE_B  (128 * 80)
#define STAGE_B (4 * TILE_B)
#define SMEM_DYN (2 * STAGE_B)        // 81920 B (>= 128*129*4 stage)

__global__ void __launch_bounds__(256, 2) gemm_mma_kernel() {
    extern __shared__ char dynsm[];
    const uint32_t smb = smem_u32(dynsm);

    const int t = threadIdx.x, wid = t >> 5, lane = t & 31;

    // triangular decode: blockIdx.x -> (bi, bj), bi >= bj
    int tidx = blockIdx.x;
    int bi = (int)((-1.0f + sqrtf(1.0f + 8.0f * (float)tidx)) * 0.5f);
    while ((bi + 1) * (bi + 2) / 2 <= tidx) ++bi;
    while (bi * (bi + 1) / 2 > tidx) --bi;
    int bj = tidx - bi * (bi + 1) / 2;
    const int i0 = bi * 128, j0 = bj * 128;

    const int warpM = wid & 1, warpN = wid >> 1;

    const int lrow = t >> 1, lh = t & 1;
    const uint4* gAhi = g_Xhi4 + (size_t)(i0 + lrow) * 32;
    const uint4* gAlo = g_Xlo4 + (size_t)(i0 + lrow) * 32;
    const uint4* gBhi = g_Xhi4 + (size_t)(j0 + lrow) * 32;
    const uint4* gBlo = g_Xlo4 + (size_t)(j0 + lrow) * 32;

    float acc[4][4][4];
    #pragma unroll
    for (int mt = 0; mt < 4; ++mt)
        #pragma unroll
        for (int nt = 0; nt < 4; ++nt)
            #pragma unroll
            for (int q = 0; q < 4; ++q) acc[mt][nt][q] = 0.0f;

    const int arow = (lane & 15), akoff = (lane >> 4) * 16;
    const int brow = (lane & 7),  bkoff = ((lane >> 3) & 1) * 16;

    auto issue_stage = [&](int c, int b) {
        uint32_t st = smb + b * STAGE_B;
        #pragma unroll
        for (int q = 0; q < 2; ++q) {
            int idx = lh * 2 + q;
            uint32_t off = (uint32_t)(lrow * 80 + idx * 16);
            int go = c * 4 + idx;
            cp16(st + 0 * TILE_B + off, gAhi + go);
            cp16(st + 1 * TILE_B + off, gAlo + go);
            cp16(st + 2 * TILE_B + off, gBhi + go);
            cp16(st + 3 * TILE_B + off, gBlo + go);
        }
        CP_COMMIT();
    };

    issue_stage(0, 0);

    for (int c = 0; c < NCHUNK; ++c) {
        const int b = c & 1;
        if (c + 1 < NCHUNK) {
            issue_stage(c + 1, (c + 1) & 1);
            CP_WAIT(1);
        } else {
            CP_WAIT(0);
        }
        __syncthreads();

        const uint32_t st = smb + b * STAGE_B;
        #pragma unroll
        for (int ks = 0; ks < 2; ++ks) {
            const int kb = ks * 32;
            uint32_t Ahi[4][4], Alo[4][4];
            #pragma unroll
            for (int mt = 0; mt < 4; ++mt) {
                uint32_t a = st + (uint32_t)((warpM * 64 + mt * 16 + arow) * 80 + kb + akoff);
                ldsm_x4(Ahi[mt][0], Ahi[mt][1], Ahi[mt][2], Ahi[mt][3], a + 0 * TILE_B);
                ldsm_x4(Alo[mt][0], Alo[mt][1], Alo[mt][2], Alo[mt][3], a + 1 * TILE_B);
            }
            #pragma unroll
            for (int nt = 0; nt < 4; ++nt) {
                uint32_t ba = st + (uint32_t)((warpN * 32 + nt * 8 + brow) * 80 + kb + bkoff);
                uint32_t Bhi[2], Blo[2];
                ldsm_x2(Bhi[0], Bhi[1], ba + 2 * TILE_B);
                ldsm_x2(Blo[0], Blo[1], ba + 3 * TILE_B);
                #pragma unroll
                for (int mt = 0; mt < 4; ++mt) {
                    mma16816(acc[mt][nt], Ahi[mt], Bhi);
                    mma16816(acc[mt][nt], Alo[mt], Bhi);
                    mma16816(acc[mt][nt], Ahi[mt], Blo);
                }
            }
        }
        __syncthreads();
    }

    // ---- stage dot tile in smem ----
    float* stg = reinterpret_cast<float*>(dynsm);      // 128 x 129 floats
    const int gq = lane >> 2, tig = lane & 3;
    #pragma unroll
    for (int nt = 0; nt < 4; ++nt) {
        const int col = warpN * 32 + nt * 8 + tig * 2;
        #pragma unroll
        for (int mt = 0; mt < 4; ++mt) {
            const int r0 = warpM * 64 + mt * 16 + gq;
            float* d = acc[mt][nt];
            stg[r0 * 129 + col]           = d[0];
            stg[r0 * 129 + col + 1]       = d[1];
            stg[(r0 + 8) * 129 + col]     = d[2];
            stg[(r0 + 8) * 129 + col + 1] = d[3];
        }
    }
    __syncthreads();

    // ---- fused per-tile top-10 scan (register-resident sorted list) ----
    // threads 0-127: normal rows (row=i0+r, cols j0+c, coltile bj)
    // threads 128-255: transposed rows (row=j0+r, cols i0+c, coltile bi), off-diag only
    const bool trans = (t >= 128);
    if (!trans || bi != bj) {
        const int r = t & 127;
        float v[Kn]; int id[Kn];
        #pragma unroll
        for (int k = 0; k < Kn; ++k) { v[k] = 3.4e38f; id[k] = -1; }

        if (!trans) {
            const float* srow = &stg[r * 129];
            const bool diag = (bi == bj);
            #pragma unroll 4
            for (int c = 0; c < 128; ++c) {
                float s = g_Xsq[j0 + c] - 2.0f * srow[c];
                if (diag && c == r) s = 3.4e38f;
                TOP10_INSERT(s, j0 + c, v, id)
            }
            float2* dst = &g_cand[((size_t)(i0 + r) * NTILE + bj) * Kn];
            #pragma unroll
            for (int k = 0; k < Kn; ++k)
                dst[k] = make_float2(v[k], __int_as_float(id[k]));
        } else {
            #pragma unroll 4
            for (int c = 0; c < 128; ++c) {
                float s = g_Xsq[i0 + c] - 2.0f * stg[c * 129 + r];
                TOP10_INSERT(s, i0 + c, v, id)
            }
            float2* dst = &g_cand[((size_t)(j0 + r) * NTILE + bi) * Kn];
            #pragma unroll
            for (int k = 0; k < Kn; ++k)
                dst[k] = make_float2(v[k], __int_as_float(id[k]));
        }
    }
}

// ---------------- kernel 3: merge 64 sorted-10 lists per row ---------------
__global__ void __launch_bounds__(64) topk_merge_kernel() {
    const int row = blockIdx.x;
    const int tid = threadIdx.x;

    __shared__ float sv[64][Kn];
    __shared__ int   si[64][Kn];

    const float2* src = &g_cand[((size_t)row * NTILE + tid) * Kn];
    #pragma unroll
    for (int k = 0; k < Kn; ++k) {
        float2 p = src[k];
        sv[tid][k] = p.x;
        si[tid][k] = __float_as_int(p.y);
    }

    for (int step = 32; step >= 1; step >>= 1) {
        __syncthreads();
        if (tid < step) {
            float av[Kn]; int ai[Kn];
            #pragma unroll
            for (int k = 0; k < Kn; ++k) { av[k] = sv[tid][k]; ai[k] = si[tid][k]; }
            int ia = 0, ib = 0;
            float ov[Kn]; int oi[Kn];
            #pragma unroll
            for (int k = 0; k < Kn; ++k) {
                float bvv = sv[tid + step][ib];
                if (av[ia] <= bvv) { ov[k] = av[ia]; oi[k] = ai[ia]; ++ia; }
                else               { ov[k] = bvv;    oi[k] = si[tid + step][ib]; ++ib; }
            }
            #pragma unroll
            for (int k = 0; k < Kn; ++k) { sv[tid][k] = ov[k]; si[tid][k] = oi[k]; }
        }
    }
    __syncthreads();
    if (tid < Kn) g_nbr[row * Kn + tid] = si[0][tid];
}

// ---------------- kernel 4: per-row loss ----------------------------------
__global__ void __launch_bounds__(320) loss_kernel(const float* __restrict__ X,
                                                   const float* __restrict__ Z) {
    const int i = blockIdx.x;
    const int w = threadIdx.x >> 5;
    const int l = threadIdx.x & 31;
    __shared__ float xd[Kn], zd[Kn];

    int nb = g_nbr[i * Kn + w];
    const float* xi = X + (size_t)i  * Dd;
    const float* xn = X + (size_t)nb * Dd;
    float sx = 0.0f;
    #pragma unroll
    for (int d = 0; d < Dd; d += 32) {
        float df = xi[d + l] - xn[d + l];
        sx = fmaf(df, df, sx);
    }
    const float* zi = Z + (size_t)i  * 64;
    const float* zn = Z + (size_t)nb * 64;
    float sz = 0.0f;
    #pragma unroll
    for (int d = 0; d < 64; d += 32) {
        float df = zi[d + l] - zn[d + l];
        sz = fmaf(df, df, sz);
    }
    #pragma unroll
    for (int o = 16; o > 0; o >>= 1) {
        sx += __shfl_xor_sync(0xFFFFFFFFu, sx, o);
        sz += __shfl_xor_sync(0xFFFFFFFFu, sz, o);
    }
    if (l == 0) { xd[w] = sqrtf(sx); zd[w] = sqrtf(sz); }
    __syncthreads();
    if (threadIdx.x == 0) {
        float xm = 0.0f, zm = 0.0f;
        #pragma unroll
        for (int k = 0; k < Kn; ++k) { xm = fmaxf(xm, xd[k]); zm = fmaxf(zm, zd[k]); }
        xm = fmaxf(xm, 1e-8f);
        zm = fmaxf(zm, 1e-8f);
        float s = 0.0f;
        #pragma unroll
        for (int k = 0; k < Kn; ++k) s += fabsf(xd[k] / xm - zd[k] / zm);
        g_rowsum[i] = s;
    }
}

// ---------------- kernel 5: deterministic final reduction ------------------
__global__ void __launch_bounds__(1024) reduce_kernel(float* __restrict__ out) {
    __shared__ float sm[1024];
    int t = threadIdx.x;
    float s = 0.0f;
    for (int i = t; i < Nn; i += 1024) s += g_rowsum[i];
    sm[t] = s;
    __syncthreads();
    for (int st = 512; st > 0; st >>= 1) {
        if (t < st) sm[t] += sm[t + st];
        __syncthreads();
    }
    if (t == 0) out[0] = sm[0] / (float)(Nn * Kn);
}

// ---------------- launch ---------------------------------------------------
extern "C" void kernel_launch(void* const* d_in, const int* in_sizes, int n_in,
                              void* d_out, int out_size) {
    const float* z = (const float*)d_in[0];
    const float* X = (const float*)d_in[1];
    if (n_in >= 2 && in_sizes[0] != Nn * 64) {
        z = (const float*)d_in[1];
        X = (const float*)d_in[0];
    }
    float* out = (float*)d_out;

    cudaFuncSetAttribute(gemm_mma_kernel, cudaFuncAttributeMaxDynamicSharedMemorySize, SMEM_DYN);

    convert_kernel<<<Nn * Dd / 8 / 256, 256>>>(X);
    xsq_kernel<<<Nn / 8, 256>>>(X);
    gemm_mma_kernel<<<NTILE * (NTILE + 1) / 2, 256, SMEM_DYN>>>();
    topk_merge_kernel<<<Nn, 64>>>();
    loss_kernel<<<Nn, 320>>>(X, z);
    reduce_kernel<<<1, 1024>>>(out);
}

// round 6
// speedup vs baseline: 5.5950x; 1.0388x over previous
#include <cuda_runtime.h>
#include <cuda_bf16.h>
#include <cstdint>

#define Nn 8192
#define Dd 256
#define Kn 10
#define NTILE 64                      // Nn / 128

// ---------------- scratch (device globals) ---------------------------------
__device__ float g_Xsq[Nn];
__device__ float2 g_cand[(size_t)NTILE * Nn * Kn];   // 42 MB: [tile][row][10]
__device__ int   g_nbr[Nn * Kn];
__device__ float g_rowsum[Nn];
// K-chunk-major bf16 halves: [chunk c (32 elems)][row][4 x uint4]
__device__ uint4 g_Xhi4[Nn * Dd / 8];
__device__ uint4 g_Xlo4[Nn * Dd / 8];

// ---------------- helpers --------------------------------------------------
__device__ __forceinline__ uint32_t smem_u32(const void* p) {
    uint32_t a;
    asm("{ .reg .u64 t; cvta.to.shared.u64 t, %1; cvt.u32.u64 %0, t; }" : "=r"(a) : "l"(p));
    return a;
}
__device__ __forceinline__ void cp16(uint32_t s, const void* g) {
    asm volatile("cp.async.cg.shared.global [%0], [%1], 16;" :: "r"(s), "l"(g));
}
#define CP_COMMIT() asm volatile("cp.async.commit_group;" ::: "memory")
#define CP_WAIT(n)  asm volatile("cp.async.wait_group %0;" :: "n"(n) : "memory")

__device__ __forceinline__ void ldsm_x4(uint32_t& r0, uint32_t& r1, uint32_t& r2, uint32_t& r3, uint32_t a) {
    asm volatile("ldmatrix.sync.aligned.m8n8.x4.shared.b16 {%0,%1,%2,%3}, [%4];"
                 : "=r"(r0), "=r"(r1), "=r"(r2), "=r"(r3) : "r"(a));
}
__device__ __forceinline__ void ldsm_x2(uint32_t& r0, uint32_t& r1, uint32_t a) {
    asm volatile("ldmatrix.sync.aligned.m8n8.x2.shared.b16 {%0,%1}, [%2];"
                 : "=r"(r0), "=r"(r1) : "r"(a));
}
__device__ __forceinline__ void mma16816(float* d, const uint32_t* a, const uint32_t* b) {
    asm volatile("mma.sync.aligned.m16n8k16.row.col.f32.bf16.bf16.f32 "
                 "{%0,%1,%2,%3}, {%4,%5,%6,%7}, {%8,%9}, {%0,%1,%2,%3};"
                 : "+f"(d[0]), "+f"(d[1]), "+f"(d[2]), "+f"(d[3])
                 : "r"(a[0]), "r"(a[1]), "r"(a[2]), "r"(a[3]), "r"(b[0]), "r"(b[1]));
}

// register-resident sorted-10 insert (static indices only -> no local mem)
#define TOP10_INSERT(s, j, v, id)                                              \
    if ((s) < v[9]) {                                                          \
        v[9] = (s); id[9] = (j);                                               \
        _Pragma("unroll")                                                      \
        for (int _k = 8; _k >= 0; --_k) {                                      \
            if (v[_k + 1] < v[_k]) {                                           \
                float _tv = v[_k]; v[_k] = v[_k + 1]; v[_k + 1] = _tv;         \
                int _ti = id[_k]; id[_k] = id[_k + 1]; id[_k + 1] = _ti;       \
            }                                                                  \
        }                                                                      \
    }

// ---------------- kernel 0: fp32 -> bf16 hi/lo split (K-chunk-major) -------
__global__ void convert_kernel(const float* __restrict__ X) {
    int i = blockIdx.x * 256 + threadIdx.x;    // uint4 index, Nn*32 total
    int r = i >> 5;                            // row
    int q = i & 31;                            // uint4 within row
    int c = q >> 2;                            // k-chunk (32 elems)
    int p = q & 3;                             // uint4 within chunk
    const float4* xp = reinterpret_cast<const float4*>(X) + (size_t)i * 2;
    float4 a = xp[0], b = xp[1];
    float v[8] = {a.x, a.y, a.z, a.w, b.x, b.y, b.z, b.w};
    __nv_bfloat16 hi[8], lo[8];
    #pragma unroll
    for (int k = 0; k < 8; ++k) {
        hi[k] = __float2bfloat16(v[k]);
        lo[k] = __float2bfloat16(v[k] - __bfloat162float(hi[k]));
    }
    size_t dst = ((size_t)c * Nn + r) * 4 + p;
    g_Xhi4[dst] = *reinterpret_cast<uint4*>(hi);
    g_Xlo4[dst] = *reinterpret_cast<uint4*>(lo);
}

// ---------------- kernel 1: row sums of squares ----------------------------
__global__ void xsq_kernel(const float* __restrict__ X) {
    int row  = blockIdx.x * 8 + (threadIdx.x >> 5);
    int lane = threadIdx.x & 31;
    const float4* xr = reinterpret_cast<const float4*>(X + (size_t)row * Dd);
    float4 u = xr[lane];
    float4 v = xr[lane + 32];
    float s = u.x*u.x + u.y*u.y + u.z*u.z + u.w*u.w
            + v.x*v.x + v.y*v.y + v.z*v.z + v.w*v.w;
    #pragma unroll
    for (int o = 16; o > 0; o >>= 1) s += __shfl_xor_sync(0xFFFFFFFFu, s, o);
    if (lane == 0) g_Xsq[row] = s;
}

// ---------------- kernel 2: symmetric HMMA GEMM + fused per-tile top-10 ----
#define BKc     32
#define NCHUNK  (Dd / BKc)            // 8
#define TILE_B  (128 * 80)
#define STAGE_B (4 * TILE_B)
#define SMEM_DYN (2 * STAGE_B)        // 81920 B (>= 128*129*4 stage)

__global__ void __launch_bounds__(256, 2) gemm_mma_kernel() {
    extern __shared__ char dynsm[];
    __shared__ float sXsq[256];
    const uint32_t smb = smem_u32(dynsm);

    const int t = threadIdx.x, wid = t >> 5, lane = t & 31;

    // triangular decode: blockIdx.x -> (bi, bj), bi >= bj
    int tidx = blockIdx.x;
    int bi = (int)((-1.0f + sqrtf(1.0f + 8.0f * (float)tidx)) * 0.5f);
    while ((bi + 1) * (bi + 2) / 2 <= tidx) ++bi;
    while (bi * (bi + 1) / 2 > tidx) --bi;
    int bj = tidx - bi * (bi + 1) / 2;
    const int i0 = bi * 128, j0 = bj * 128;

    const int warpM = wid & 1, warpN = wid >> 1;

    // ---- load mapping: thread t loads 32B of one row per tile ----
    const int lrow = t >> 1, lh = t & 1;

    float acc[4][4][4];
    #pragma unroll
    for (int mt = 0; mt < 4; ++mt)
        #pragma unroll
        for (int nt = 0; nt < 4; ++nt)
            #pragma unroll
            for (int q = 0; q < 4; ++q) acc[mt][nt][q] = 0.0f;

    const int arow = (lane & 15), akoff = (lane >> 4) * 16;
    const int brow = (lane & 7),  bkoff = ((lane >> 3) & 1) * 16;

    auto issue_stage = [&](int c, int b) {
        uint32_t st = smb + b * STAGE_B;
        uint32_t off = (uint32_t)(lrow * 80 + lh * 32);
        size_t cb = (size_t)c * Nn * 4;
        size_t ga = cb + (size_t)(i0 + lrow) * 4 + lh * 2;
        size_t gb = cb + (size_t)(j0 + lrow) * 4 + lh * 2;
        cp16(st + 0 * TILE_B + off,      g_Xhi4 + ga);
        cp16(st + 0 * TILE_B + off + 16, g_Xhi4 + ga + 1);
        cp16(st + 1 * TILE_B + off,      g_Xlo4 + ga);
        cp16(st + 1 * TILE_B + off + 16, g_Xlo4 + ga + 1);
        cp16(st + 2 * TILE_B + off,      g_Xhi4 + gb);
        cp16(st + 2 * TILE_B + off + 16, g_Xhi4 + gb + 1);
        cp16(st + 3 * TILE_B + off,      g_Xlo4 + gb);
        cp16(st + 3 * TILE_B + off + 16, g_Xlo4 + gb + 1);
        CP_COMMIT();
    };

    issue_stage(0, 0);
    // preload Xsq tiles for the scan phase
    if (t < 128) sXsq[t] = g_Xsq[j0 + t];
    else         sXsq[t] = g_Xsq[i0 + (t - 128)];

    for (int c = 0; c < NCHUNK; ++c) {
        const int b = c & 1;
        if (c + 1 < NCHUNK) {
            issue_stage(c + 1, (c + 1) & 1);
            CP_WAIT(1);
        } else {
            CP_WAIT(0);
        }
        __syncthreads();

        const uint32_t st = smb + b * STAGE_B;
        #pragma unroll
        for (int ks = 0; ks < 2; ++ks) {
            const int kb = ks * 32;
            uint32_t Ahi[4][4], Alo[4][4];
            #pragma unroll
            for (int mt = 0; mt < 4; ++mt) {
                uint32_t a = st + (uint32_t)((warpM * 64 + mt * 16 + arow) * 80 + kb + akoff);
                ldsm_x4(Ahi[mt][0], Ahi[mt][1], Ahi[mt][2], Ahi[mt][3], a + 0 * TILE_B);
                ldsm_x4(Alo[mt][0], Alo[mt][1], Alo[mt][2], Alo[mt][3], a + 1 * TILE_B);
            }
            #pragma unroll
            for (int nt = 0; nt < 4; ++nt) {
                uint32_t ba = st + (uint32_t)((warpN * 32 + nt * 8 + brow) * 80 + kb + bkoff);
                uint32_t Bhi[2], Blo[2];
                ldsm_x2(Bhi[0], Bhi[1], ba + 2 * TILE_B);
                ldsm_x2(Blo[0], Blo[1], ba + 3 * TILE_B);
                #pragma unroll
                for (int mt = 0; mt < 4; ++mt) {
                    mma16816(acc[mt][nt], Ahi[mt], Bhi);
                    mma16816(acc[mt][nt], Alo[mt], Bhi);
                    mma16816(acc[mt][nt], Ahi[mt], Blo);
                }
            }
        }
        __syncthreads();
    }

    // ---- stage dot tile in smem ----
    float* stg = reinterpret_cast<float*>(dynsm);      // 128 x 129 floats
    const int gq = lane >> 2, tig = lane & 3;
    #pragma unroll
    for (int nt = 0; nt < 4; ++nt) {
        const int col = warpN * 32 + nt * 8 + tig * 2;
        #pragma unroll
        for (int mt = 0; mt < 4; ++mt) {
            const int r0 = warpM * 64 + mt * 16 + gq;
            float* d = acc[mt][nt];
            stg[r0 * 129 + col]           = d[0];
            stg[r0 * 129 + col + 1]       = d[1];
            stg[(r0 + 8) * 129 + col]     = d[2];
            stg[(r0 + 8) * 129 + col + 1] = d[3];
        }
    }
    __syncthreads();

    // ---- fused per-tile top-10 scan (register-resident sorted list) ----
    const bool trans = (t >= 128);
    if (!trans || bi != bj) {
        const int r = t & 127;
        float v[Kn]; int id[Kn];
        #pragma unroll
        for (int k = 0; k < Kn; ++k) { v[k] = 3.4e38f; id[k] = -1; }

        if (!trans) {
            const float* srow = &stg[r * 129];
            const bool diag = (bi == bj);
            #pragma unroll 4
            for (int c = 0; c < 128; ++c) {
                float s = sXsq[c] - 2.0f * srow[c];
                if (diag && c == r) s = 3.4e38f;
                TOP10_INSERT(s, j0 + c, v, id)
            }
            float2* dst = &g_cand[((size_t)bj * Nn + (i0 + r)) * Kn];
            #pragma unroll
            for (int k = 0; k < Kn; ++k)
                dst[k] = make_float2(v[k], __int_as_float(id[k]));
        } else {
            #pragma unroll 4
            for (int c = 0; c < 128; ++c) {
                float s = sXsq[128 + c] - 2.0f * stg[c * 129 + r];
                TOP10_INSERT(s, i0 + c, v, id)
            }
            float2* dst = &g_cand[((size_t)bi * Nn + (j0 + r)) * Kn];
            #pragma unroll
            for (int k = 0; k < Kn; ++k)
                dst[k] = make_float2(v[k], __int_as_float(id[k]));
        }
    }
}

// ---------------- kernel 3: merge 64 sorted-10 lists per row (4 rows/CTA) --
__global__ void __launch_bounds__(256) topk_merge_kernel() {
    const int tid = threadIdx.x;
    const int grp = tid >> 6, t = tid & 63;
    const int row = blockIdx.x * 4 + grp;

    __shared__ float sv[4][64][Kn];
    __shared__ int   si[4][64][Kn];

    const float2* src = &g_cand[((size_t)t * Nn + row) * Kn];
    #pragma unroll
    for (int k = 0; k < Kn; ++k) {
        float2 p = src[k];
        sv[grp][t][k] = p.x;
        si[grp][t][k] = __float_as_int(p.y);
    }

    for (int step = 32; step >= 1; step >>= 1) {
        __syncthreads();
        if (t < step) {
            float av[Kn]; int ai[Kn];
            #pragma unroll
            for (int k = 0; k < Kn; ++k) { av[k] = sv[grp][t][k]; ai[k] = si[grp][t][k]; }
            int ia = 0, ib = 0;
            float ov[Kn]; int oi[Kn];
            #pragma unroll
            for (int k = 0; k < Kn; ++k) {
                float bvv = sv[grp][t + step][ib];
                if (av[ia] <= bvv) { ov[k] = av[ia]; oi[k] = ai[ia]; ++ia; }
                else               { ov[k] = bvv;    oi[k] = si[grp][t + step][ib]; ++ib; }
            }
            #pragma unroll
            for (int k = 0; k < Kn; ++k) { sv[grp][t][k] = ov[k]; si[grp][t][k] = oi[k]; }
        }
    }
    __syncthreads();
    if (t < Kn) g_nbr[row * Kn + t] = si[grp][0][t];
}

// ---------------- kernel 4: per-row loss ----------------------------------
__global__ void __launch_bounds__(320) loss_kernel(const float* __restrict__ X,
                                                   const float* __restrict__ Z) {
    const int i = blockIdx.x;
    const int w = threadIdx.x >> 5;
    const int l = threadIdx.x & 31;
    __shared__ float xd[Kn], zd[Kn];

    int nb = g_nbr[i * Kn + w];
    const float* xi = X + (size_t)i  * Dd;
    const float* xn = X + (size_t)nb * Dd;
    float sx = 0.0f;
    #pragma unroll
    for (int d = 0; d < Dd; d += 32) {
        float df = xi[d + l] - xn[d + l];
        sx = fmaf(df, df, sx);
    }
    const float* zi = Z + (size_t)i  * 64;
    const float* zn = Z + (size_t)nb * 64;
    float sz = 0.0f;
    #pragma unroll
    for (int d = 0; d < 64; d += 32) {
        float df = zi[d + l] - zn[d + l];
        sz = fmaf(df, df, sz);
    }
    #pragma unroll
    for (int o = 16; o > 0; o >>= 1) {
        sx += __shfl_xor_sync(0xFFFFFFFFu, sx, o);
        sz += __shfl_xor_sync(0xFFFFFFFFu, sz, o);
    }
    if (l == 0) { xd[w] = sqrtf(sx); zd[w] = sqrtf(sz); }
    __syncthreads();
    if (threadIdx.x == 0) {
        float xm = 0.0f, zm = 0.0f;
        #pragma unroll
        for (int k = 0; k < Kn; ++k) { xm = fmaxf(xm, xd[k]); zm = fmaxf(zm, zd[k]); }
        xm = fmaxf(xm, 1e-8f);
        zm = fmaxf(zm, 1e-8f);
        float s = 0.0f;
        #pragma unroll
        for (int k = 0; k < Kn; ++k) s += fabsf(xd[k] / xm - zd[k] / zm);
        g_rowsum[i] = s;
    }
}

// ---------------- kernel 5: deterministic final reduction ------------------
__global__ void __launch_bounds__(1024) reduce_kernel(float* __restrict__ out) {
    __shared__ float sm[1024];
    int t = threadIdx.x;
    float s = 0.0f;
    for (int i = t; i < Nn; i += 1024) s += g_rowsum[i];
    sm[t] = s;
    __syncthreads();
    for (int st = 512; st > 0; st >>= 1) {
        if (t < st) sm[t] += sm[t + st];
        __syncthreads();
    }
    if (t == 0) out[0] = sm[0] / (float)(Nn * Kn);
}

// ---------------- launch ---------------------------------------------------
extern "C" void kernel_launch(void* const* d_in, const int* in_sizes, int n_in,
                              void* d_out, int out_size) {
    const float* z = (const float*)d_in[0];
    const float* X = (const float*)d_in[1];
    if (n_in >= 2 && in_sizes[0] != Nn * 64) {
        z = (const float*)d_in[1];
        X = (const float*)d_in[0];
    }
    float* out = (float*)d_out;

    cudaFuncSetAttribute(gemm_mma_kernel, cudaFuncAttributeMaxDynamicSharedMemorySize, SMEM_DYN);

    convert_kernel<<<Nn * 32 / 256, 256>>>(X);
    xsq_kernel<<<Nn / 8, 256>>>(X);
    gemm_mma_kernel<<<NTILE * (NTILE + 1) / 2, 256, SMEM_DYN>>>();
    topk_merge_kernel<<<Nn / 4, 256>>>();
    loss_kernel<<<Nn, 320>>>(X, z);
    reduce_kernel<<<1, 1024>>>(out);
}

// round 8
// speedup vs baseline: 5.9238x; 1.0588x over previous
#include <cuda_runtime.h>
#include <cuda_bf16.h>
#include <cstdint>

#define Nn 8192
#define Dd 256
#define Kn 10
#define NTILE 64                      // Nn / 128

// ---------------- scratch (device globals) ---------------------------------
__device__ float g_Xsq[Nn];
__device__ float2 g_cand[(size_t)Nn * NTILE * Kn];   // 42 MB: [row][tile][10]
__device__ int   g_nbr[Nn * Kn];
__device__ float g_rowsum[Nn];
// K-chunk-major bf16 halves: [chunk c (32 elems)][row][4 x uint4]
__device__ uint4 g_Xhi4[Nn * Dd / 8];
__device__ uint4 g_Xlo4[Nn * Dd / 8];

// ---------------- helpers --------------------------------------------------
__device__ __forceinline__ uint32_t smem_u32(const void* p) {
    uint32_t a;
    asm("{ .reg .u64 t; cvta.to.shared.u64 t, %1; cvt.u32.u64 %0, t; }" : "=r"(a) : "l"(p));
    return a;
}
__device__ __forceinline__ void cp16(uint32_t s, const void* g) {
    asm volatile("cp.async.cg.shared.global [%0], [%1], 16;" :: "r"(s), "l"(g));
}
#define CP_COMMIT() asm volatile("cp.async.commit_group;" ::: "memory")
#define CP_WAIT(n)  asm volatile("cp.async.wait_group %0;" :: "n"(n) : "memory")

__device__ __forceinline__ void ldsm_x4(uint32_t& r0, uint32_t& r1, uint32_t& r2, uint32_t& r3, uint32_t a) {
    asm volatile("ldmatrix.sync.aligned.m8n8.x4.shared.b16 {%0,%1,%2,%3}, [%4];"
                 : "=r"(r0), "=r"(r1), "=r"(r2), "=r"(r3) : "r"(a));
}
__device__ __forceinline__ void mma16816(float* d, const uint32_t* a, const uint32_t* b) {
    asm volatile("mma.sync.aligned.m16n8k16.row.col.f32.bf16.bf16.f32 "
                 "{%0,%1,%2,%3}, {%4,%5,%6,%7}, {%8,%9}, {%0,%1,%2,%3};"
                 : "+f"(d[0]), "+f"(d[1]), "+f"(d[2]), "+f"(d[3])
                 : "r"(a[0]), "r"(a[1]), "r"(a[2]), "r"(a[3]), "r"(b[0]), "r"(b[1]));
}

// register-resident sorted-10 insert (static indices only -> no local mem)
#define TOP10_INSERT(s, j, v, id)                                              \
    if ((s) < v[9]) {                                                          \
        v[9] = (s); id[9] = (j);                                               \
        _Pragma("unroll")                                                      \
        for (int _k = 8; _k >= 0; --_k) {                                      \
            if (v[_k + 1] < v[_k]) {                                           \
                float _tv = v[_k]; v[_k] = v[_k + 1]; v[_k + 1] = _tv;         \
                int _ti = id[_k]; id[_k] = id[_k + 1]; id[_k + 1] = _ti;       \
            }                                                                  \
        }                                                                      \
    }

// ---------------- kernel 0: fp32 -> bf16 hi/lo split (K-chunk-major) -------
__global__ void convert_kernel(const float* __restrict__ X) {
    int i = blockIdx.x * 256 + threadIdx.x;    // uint4 index, Nn*32 total
    int r = i >> 5;                            // row
    int q = i & 31;                            // uint4 within row
    int c = q >> 2;                            // k-chunk (32 elems)
    int p = q & 3;                             // uint4 within chunk
    const float4* xp = reinterpret_cast<const float4*>(X) + (size_t)i * 2;
    float4 a = xp[0], b = xp[1];
    float v[8] = {a.x, a.y, a.z, a.w, b.x, b.y, b.z, b.w};
    __nv_bfloat16 hi[8], lo[8];
    #pragma unroll
    for (int k = 0; k < 8; ++k) {
        hi[k] = __float2bfloat16(v[k]);
        lo[k] = __float2bfloat16(v[k] - __bfloat162float(hi[k]));
    }
    size_t dst = ((size_t)c * Nn + r) * 4 + p;
    g_Xhi4[dst] = *reinterpret_cast<uint4*>(hi);
    g_Xlo4[dst] = *reinterpret_cast<uint4*>(lo);
}

// ---------------- kernel 1: row sums of squares ----------------------------
__global__ void xsq_kernel(const float* __restrict__ X) {
    int row  = blockIdx.x * 8 + (threadIdx.x >> 5);
    int lane = threadIdx.x & 31;
    const float4* xr = reinterpret_cast<const float4*>(X + (size_t)row * Dd);
    float4 u = xr[lane];
    float4 v = xr[lane + 32];
    float s = u.x*u.x + u.y*u.y + u.z*u.z + u.w*u.w
            + v.x*v.x + v.y*v.y + v.z*v.z + v.w*v.w;
    #pragma unroll
    for (int o = 16; o > 0; o >>= 1) s += __shfl_xor_sync(0xFFFFFFFFu, s, o);
    if (lane == 0) g_Xsq[row] = s;
}

// ---------------- kernel 2: symmetric HMMA GEMM + fused per-tile top-10 ----
#define BKc     32
#define NCHUNK  (Dd / BKc)            // 8
#define TILE_B  (128 * 80)
#define STAGE_B (4 * TILE_B)
#define SMEM_DYN (2 * STAGE_B)        // 81920 B (>= 128*132*4 = 67584 stage)

__global__ void __launch_bounds__(256, 2) gemm_mma_kernel() {
    extern __shared__ char dynsm[];
    __shared__ __align__(16) float sXsq[256];
    const uint32_t smb = smem_u32(dynsm);

    const int t = threadIdx.x, wid = t >> 5, lane = t & 31;

    // triangular decode: blockIdx.x -> (bi, bj), bi >= bj
    int tidx = blockIdx.x;
    int bi = (int)((-1.0f + sqrtf(1.0f + 8.0f * (float)tidx)) * 0.5f);
    while ((bi + 1) * (bi + 2) / 2 <= tidx) ++bi;
    while (bi * (bi + 1) / 2 > tidx) --bi;
    int bj = tidx - bi * (bi + 1) / 2;
    const int i0 = bi * 128, j0 = bj * 128;

    const int warpM = wid & 1, warpN = wid >> 1;

    const int lrow = t >> 1, lh = t & 1;

    float acc[4][4][4];
    #pragma unroll
    for (int mt = 0; mt < 4; ++mt)
        #pragma unroll
        for (int nt = 0; nt < 4; ++nt)
            #pragma unroll
            for (int q = 0; q < 4; ++q) acc[mt][nt][q] = 0.0f;

    const int arow = (lane & 15), akoff = (lane >> 4) * 16;
    // paired-B ldsm mapping: mat m = lane>>3 -> (khalf = m&1, rowhalf = m>>1)
    const int bm = lane >> 3;
    const int brow2 = 8 * (bm >> 1) + (lane & 7);
    const int bko = 16 * (bm & 1);

    auto issue_stage = [&](int c, int b) {
        uint32_t st = smb + b * STAGE_B;
        uint32_t off = (uint32_t)(lrow * 80 + lh * 32);
        size_t cb = (size_t)c * Nn * 4;
        size_t ga = cb + (size_t)(i0 + lrow) * 4 + lh * 2;
        size_t gb = cb + (size_t)(j0 + lrow) * 4 + lh * 2;
        cp16(st + 0 * TILE_B + off,      g_Xhi4 + ga);
        cp16(st + 0 * TILE_B + off + 16, g_Xhi4 + ga + 1);
        cp16(st + 1 * TILE_B + off,      g_Xlo4 + ga);
        cp16(st + 1 * TILE_B + off + 16, g_Xlo4 + ga + 1);
        cp16(st + 2 * TILE_B + off,      g_Xhi4 + gb);
        cp16(st + 2 * TILE_B + off + 16, g_Xhi4 + gb + 1);
        cp16(st + 3 * TILE_B + off,      g_Xlo4 + gb);
        cp16(st + 3 * TILE_B + off + 16, g_Xlo4 + gb + 1);
        CP_COMMIT();
    };

    issue_stage(0, 0);
    if (t < 128) sXsq[t] = g_Xsq[j0 + t];
    else         sXsq[t] = g_Xsq[i0 + (t - 128)];

    for (int c = 0; c < NCHUNK; ++c) {
        const int b = c & 1;
        if (c + 1 < NCHUNK) {
            issue_stage(c + 1, (c + 1) & 1);
            CP_WAIT(1);
        } else {
            CP_WAIT(0);
        }
        __syncthreads();

        const uint32_t st = smb + b * STAGE_B;
        #pragma unroll
        for (int ks = 0; ks < 2; ++ks) {
            const int kb = ks * 32;
            uint32_t Ahi[4][4], Alo[4][4];
            #pragma unroll
            for (int mt = 0; mt < 4; ++mt) {
                uint32_t a = st + (uint32_t)((warpM * 64 + mt * 16 + arow) * 80 + kb + akoff);
                ldsm_x4(Ahi[mt][0], Ahi[mt][1], Ahi[mt][2], Ahi[mt][3], a + 0 * TILE_B);
                ldsm_x4(Alo[mt][0], Alo[mt][1], Alo[mt][2], Alo[mt][3], a + 1 * TILE_B);
            }
            #pragma unroll
            for (int p = 0; p < 2; ++p) {
                uint32_t ba = st + (uint32_t)((warpN * 32 + p * 16 + brow2) * 80 + kb + bko);
                uint32_t Bh[4], Bl[4];
                ldsm_x4(Bh[0], Bh[1], Bh[2], Bh[3], ba + 2 * TILE_B);
                ldsm_x4(Bl[0], Bl[1], Bl[2], Bl[3], ba + 3 * TILE_B);
                #pragma unroll
                for (int mt = 0; mt < 4; ++mt) {
                    mma16816(acc[mt][2 * p],     Ahi[mt], Bh + 0);
                    mma16816(acc[mt][2 * p],     Alo[mt], Bh + 0);
                    mma16816(acc[mt][2 * p],     Ahi[mt], Bl + 0);
                    mma16816(acc[mt][2 * p + 1], Ahi[mt], Bh + 2);
                    mma16816(acc[mt][2 * p + 1], Alo[mt], Bh + 2);
                    mma16816(acc[mt][2 * p + 1], Ahi[mt], Bl + 2);
                }
            }
        }
        __syncthreads();
    }

    // ---- stage dot tile in smem (stride 132: float4-aligned, conflict-free)
    float* stg = reinterpret_cast<float*>(dynsm);      // 128 x 132 floats
    const int gq = lane >> 2, tig = lane & 3;
    #pragma unroll
    for (int nt = 0; nt < 4; ++nt) {
        const int col = warpN * 32 + nt * 8 + tig * 2;
        #pragma unroll
        for (int mt = 0; mt < 4; ++mt) {
            const int r0 = warpM * 64 + mt * 16 + gq;
            float* d = acc[mt][nt];
            stg[r0 * 132 + col]           = d[0];
            stg[r0 * 132 + col + 1]       = d[1];
            stg[(r0 + 8) * 132 + col]     = d[2];
            stg[(r0 + 8) * 132 + col + 1] = d[3];
        }
    }
    __syncthreads();

    // ---- fused per-tile top-10 scan ----
    const bool trans = (t >= 128);
    if (!trans || bi != bj) {
        const int r = t & 127;
        float v[Kn]; int id[Kn];
        #pragma unroll
        for (int k = 0; k < Kn; ++k) { v[k] = 3.4e38f; id[k] = -1; }

        if (!trans) {
            const float4* srow4 = reinterpret_cast<const float4*>(&stg[r * 132]);
            const float4* xsq4  = reinterpret_cast<const float4*>(sXsq);
            const bool diag = (bi == bj);
            #pragma unroll 2
            for (int c4 = 0; c4 < 32; ++c4) {
                float4 dv = srow4[c4];
                float4 xq = xsq4[c4];
                float s0 = xq.x - 2.0f * dv.x;
                float s1 = xq.y - 2.0f * dv.y;
                float s2 = xq.z - 2.0f * dv.z;
                float s3 = xq.w - 2.0f * dv.w;
                int cb = c4 * 4;
                if (diag) {
                    if (cb == r)     s0 = 3.4e38f;
                    if (cb + 1 == r) s1 = 3.4e38f;
                    if (cb + 2 == r) s2 = 3.4e38f;
                    if (cb + 3 == r) s3 = 3.4e38f;
                }
                TOP10_INSERT(s0, j0 + cb,     v, id)
                TOP10_INSERT(s1, j0 + cb + 1, v, id)
                TOP10_INSERT(s2, j0 + cb + 2, v, id)
                TOP10_INSERT(s3, j0 + cb + 3, v, id)
            }
            float2* dst = &g_cand[((size_t)(i0 + r) * NTILE + bj) * Kn];
            #pragma unroll
            for (int k = 0; k < Kn; ++k)
                dst[k] = make_float2(v[k], __int_as_float(id[k]));
        } else {
            #pragma unroll 4
            for (int c = 0; c < 128; ++c) {
                float s = sXsq[128 + c] - 2.0f * stg[c * 132 + r];
                TOP10_INSERT(s, i0 + c, v, id)
            }
            float2* dst = &g_cand[((size_t)(j0 + r) * NTILE + bi) * Kn];
            #pragma unroll
            for (int k = 0; k < Kn; ++k)
                dst[k] = make_float2(v[k], __int_as_float(id[k]));
        }
    }
}

// ---------------- kernel 3: merge 64 sorted-10 lists per row (4 rows/CTA) --
__global__ void __launch_bounds__(256) topk_merge_kernel() {
    const int tid = threadIdx.x;
    const int grp = tid >> 6, t = tid & 63;
    const int row = blockIdx.x * 4 + grp;

    __shared__ float sv[4][64][Kn];
    __shared__ int   si[4][64][Kn];

    const float2* src = &g_cand[((size_t)row * NTILE + t) * Kn];
    #pragma unroll
    for (int k = 0; k < Kn; ++k) {
        float2 p = src[k];
        sv[grp][t][k] = p.x;
        si[grp][t][k] = __float_as_int(p.y);
    }

    for (int step = 32; step >= 1; step >>= 1) {
        __syncthreads();
        if (t < step) {
            float av[Kn]; int ai[Kn];
            #pragma unroll
            for (int k = 0; k < Kn; ++k) { av[k] = sv[grp][t][k]; ai[k] = si[grp][t][k]; }
            int ia = 0, ib = 0;
            float ov[Kn]; int oi[Kn];
            #pragma unroll
            for (int k = 0; k < Kn; ++k) {
                float bvv = sv[grp][t + step][ib];
                if (av[ia] <= bvv) { ov[k] = av[ia]; oi[k] = ai[ia]; ++ia; }
                else               { ov[k] = bvv;    oi[k] = si[grp][t + step][ib]; ++ib; }
            }
            #pragma unroll
            for (int k = 0; k < Kn; ++k) { sv[grp][t][k] = ov[k]; si[grp][t][k] = oi[k]; }
        }
    }
    __syncthreads();
    if (t < Kn) g_nbr[row * Kn + t] = si[grp][0][t];
}

// ---------------- kernel 4: per-row loss ----------------------------------
__global__ void __launch_bounds__(320) loss_kernel(const float* __restrict__ X,
                                                   const float* __restrict__ Z) {
    const int i = blockIdx.x;
    const int w = threadIdx.x >> 5;
    const int l = threadIdx.x & 31;
    __shared__ float xd[Kn], zd[Kn];

    int nb = g_nbr[i * Kn + w];
    const float* xi = X + (size_t)i  * Dd;
    const float* xn = X + (size_t)nb * Dd;
    float sx = 0.0f;
    #pragma unroll
    for (int d = 0; d < Dd; d += 32) {
        float df = xi[d + l] - xn[d + l];
        sx = fmaf(df, df, sx);
    }
    const float* zi = Z + (size_t)i  * 64;
    const float* zn = Z + (size_t)nb * 64;
    float sz = 0.0f;
    #pragma unroll
    for (int d = 0; d < 64; d += 32) {
        float df = zi[d + l] - zn[d + l];
        sz = fmaf(df, df, sz);
    }
    #pragma unroll
    for (int o = 16; o > 0; o >>= 1) {
        sx += __shfl_xor_sync(0xFFFFFFFFu, sx, o);
        sz += __shfl_xor_sync(0xFFFFFFFFu, sz, o);
    }
    if (l == 0) { xd[w] = sqrtf(sx); zd[w] = sqrtf(sz); }
    __syncthreads();
    if (threadIdx.x == 0) {
        float xm = 0.0f, zm = 0.0f;
        #pragma unroll
        for (int k = 0; k < Kn; ++k) { xm = fmaxf(xm, xd[k]); zm = fmaxf(zm, zd[k]); }
        xm = fmaxf(xm, 1e-8f);
        zm = fmaxf(zm, 1e-8f);
        float s = 0.0f;
        #pragma unroll
        for (int k = 0; k < Kn; ++k) s += fabsf(xd[k] / xm - zd[k] / zm);
        g_rowsum[i] = s;
    }
}

// ---------------- kernel 5: deterministic final reduction ------------------
__global__ void __launch_bounds__(1024) reduce_kernel(float* __restrict__ out) {
    __shared__ float sm[1024];
    int t = threadIdx.x;
    float s = 0.0f;
    for (int i = t; i < Nn; i += 1024) s += g_rowsum[i];
    sm[t] = s;
    __syncthreads();
    for (int st = 512; st > 0; st >>= 1) {
        if (t < st) sm[t] += sm[t + st];
        __syncthreads();
    }
    if (t == 0) out[0] = sm[0] / (float)(Nn * Kn);
}

// ---------------- launch ---------------------------------------------------
extern "C" void kernel_launch(void* const* d_in, const int* in_sizes, int n_in,
                              void* d_out, int out_size) {
    const float* z = (const float*)d_in[0];
    const float* X = (const float*)d_in[1];
    if (n_in >= 2 && in_sizes[0] != Nn * 64) {
        z = (const float*)d_in[1];
        X = (const float*)d_in[0];
    }
    float* out = (float*)d_out;

    cudaFuncSetAttribute(gemm_mma_kernel, cudaFuncAttributeMaxDynamicSharedMemorySize, SMEM_DYN);

    convert_kernel<<<Nn * 32 / 256, 256>>>(X);
    xsq_kernel<<<Nn / 8, 256>>>(X);
    gemm_mma_kernel<<<NTILE * (NTILE + 1) / 2, 256, SMEM_DYN>>>();
    topk_merge_kernel<<<Nn / 4, 256>>>();
    loss_kernel<<<Nn, 320>>>(X, z);
    reduce_kernel<<<1, 1024>>>(out);
}

// round 9
// speedup vs baseline: 5.9412x; 1.0029x over previous
#include <cuda_runtime.h>
#include <cuda_bf16.h>
#include <cstdint>

#define Nn 8192
#define Dd 256
#define Kn 10
#define NTILE 64                      // Nn / 128

// ---------------- scratch (device globals) ---------------------------------
__device__ float g_Xsq[Nn];
__device__ float2 g_cand[(size_t)Nn * NTILE * Kn];   // 42 MB: [row][tile][10]
__device__ int   g_nbr[Nn * Kn];
__device__ float g_rowsum[Nn];
// K-chunk-major bf16 halves: [chunk c (32 elems)][row][4 x uint4]
__device__ uint4 g_Xhi4[Nn * Dd / 8];
__device__ uint4 g_Xlo4[Nn * Dd / 8];

// ---------------- helpers --------------------------------------------------
__device__ __forceinline__ uint32_t smem_u32(const void* p) {
    uint32_t a;
    asm("{ .reg .u64 t; cvta.to.shared.u64 t, %1; cvt.u32.u64 %0, t; }" : "=r"(a) : "l"(p));
    return a;
}
__device__ __forceinline__ void cp16(uint32_t s, const void* g) {
    asm volatile("cp.async.cg.shared.global [%0], [%1], 16;" :: "r"(s), "l"(g));
}
#define CP_COMMIT() asm volatile("cp.async.commit_group;" ::: "memory")
#define CP_WAIT(n)  asm volatile("cp.async.wait_group %0;" :: "n"(n) : "memory")

__device__ __forceinline__ void ldsm_x4(uint32_t& r0, uint32_t& r1, uint32_t& r2, uint32_t& r3, uint32_t a) {
    asm volatile("ldmatrix.sync.aligned.m8n8.x4.shared.b16 {%0,%1,%2,%3}, [%4];"
                 : "=r"(r0), "=r"(r1), "=r"(r2), "=r"(r3) : "r"(a));
}
__device__ __forceinline__ void mma16816(float* d, const uint32_t* a, const uint32_t* b) {
    asm volatile("mma.sync.aligned.m16n8k16.row.col.f32.bf16.bf16.f32 "
                 "{%0,%1,%2,%3}, {%4,%5,%6,%7}, {%8,%9}, {%0,%1,%2,%3};"
                 : "+f"(d[0]), "+f"(d[1]), "+f"(d[2]), "+f"(d[3])
                 : "r"(a[0]), "r"(a[1]), "r"(a[2]), "r"(a[3]), "r"(b[0]), "r"(b[1]));
}

// register-resident sorted-10 insert (static indices only -> no local mem)
#define TOP10_INSERT(s, j, v, id)                                              \
    if ((s) < v[9]) {                                                          \
        v[9] = (s); id[9] = (j);                                               \
        _Pragma("unroll")                                                      \
        for (int _k = 8; _k >= 0; --_k) {                                      \
            if (v[_k + 1] < v[_k]) {                                           \
                float _tv = v[_k]; v[_k] = v[_k + 1]; v[_k + 1] = _tv;         \
                int _ti = id[_k]; id[_k] = id[_k + 1]; id[_k + 1] = _ti;       \
            }                                                                  \
        }                                                                      \
    }

// ---------------- kernel 0: fp32 -> bf16 hi/lo split + fused Xsq -----------
__global__ void convert_kernel(const float* __restrict__ X) {
    int i = blockIdx.x * 256 + threadIdx.x;    // uint4 index, Nn*32 total
    int lane = threadIdx.x & 31;
    int r = i >> 5;                            // row (one row per warp)
    int q = i & 31;                            // uint4 within row (== lane)
    int c = q >> 2;                            // k-chunk (32 elems)
    int p = q & 3;                             // uint4 within chunk
    const float4* xp = reinterpret_cast<const float4*>(X) + (size_t)i * 2;
    float4 a = xp[0], b = xp[1];
    float v[8] = {a.x, a.y, a.z, a.w, b.x, b.y, b.z, b.w};
    __nv_bfloat16 hi[8], lo[8];
    float s = 0.0f;
    #pragma unroll
    for (int k = 0; k < 8; ++k) {
        s = fmaf(v[k], v[k], s);
        hi[k] = __float2bfloat16(v[k]);
        lo[k] = __float2bfloat16(v[k] - __bfloat162float(hi[k]));
    }
    size_t dst = ((size_t)c * Nn + r) * 4 + p;
    g_Xhi4[dst] = *reinterpret_cast<uint4*>(hi);
    g_Xlo4[dst] = *reinterpret_cast<uint4*>(lo);
    #pragma unroll
    for (int o = 16; o > 0; o >>= 1) s += __shfl_xor_sync(0xFFFFFFFFu, s, o);
    if (lane == 0) g_Xsq[r] = s;
}

// ---------------- kernel 2: symmetric HMMA GEMM + fused per-tile top-10 ----
#define BKc     32
#define NCHUNK  (Dd / BKc)            // 8
#define TILE_B  (128 * 80)
#define STAGE_B (4 * TILE_B)
#define SMEM_DYN (2 * STAGE_B)        // 81920 B (>= 128*132*4 = 67584 stage)

__global__ void __launch_bounds__(256, 2) gemm_mma_kernel() {
    extern __shared__ char dynsm[];
    __shared__ __align__(16) float sXsq[256];
    const uint32_t smb = smem_u32(dynsm);

    const int t = threadIdx.x, wid = t >> 5, lane = t & 31;

    // triangular decode: blockIdx.x -> (bi, bj), bi >= bj
    int tidx = blockIdx.x;
    int bi = (int)((-1.0f + sqrtf(1.0f + 8.0f * (float)tidx)) * 0.5f);
    while ((bi + 1) * (bi + 2) / 2 <= tidx) ++bi;
    while (bi * (bi + 1) / 2 > tidx) --bi;
    int bj = tidx - bi * (bi + 1) / 2;
    const int i0 = bi * 128, j0 = bj * 128;

    const int warpM = wid & 1, warpN = wid >> 1;

    const int lrow = t >> 1, lh = t & 1;

    float acc[4][4][4];
    #pragma unroll
    for (int mt = 0; mt < 4; ++mt)
        #pragma unroll
        for (int nt = 0; nt < 4; ++nt)
            #pragma unroll
            for (int q = 0; q < 4; ++q) acc[mt][nt][q] = 0.0f;

    const int arow = (lane & 15), akoff = (lane >> 4) * 16;
    const int bm = lane >> 3;
    const int brow2 = 8 * (bm >> 1) + (lane & 7);
    const int bko = 16 * (bm & 1);

    auto issue_stage = [&](int c, int b) {
        uint32_t st = smb + b * STAGE_B;
        uint32_t off = (uint32_t)(lrow * 80 + lh * 32);
        size_t cb = (size_t)c * Nn * 4;
        size_t ga = cb + (size_t)(i0 + lrow) * 4 + lh * 2;
        size_t gb = cb + (size_t)(j0 + lrow) * 4 + lh * 2;
        cp16(st + 0 * TILE_B + off,      g_Xhi4 + ga);
        cp16(st + 0 * TILE_B + off + 16, g_Xhi4 + ga + 1);
        cp16(st + 1 * TILE_B + off,      g_Xlo4 + ga);
        cp16(st + 1 * TILE_B + off + 16, g_Xlo4 + ga + 1);
        cp16(st + 2 * TILE_B + off,      g_Xhi4 + gb);
        cp16(st + 2 * TILE_B + off + 16, g_Xhi4 + gb + 1);
        cp16(st + 3 * TILE_B + off,      g_Xlo4 + gb);
        cp16(st + 3 * TILE_B + off + 16, g_Xlo4 + gb + 1);
        CP_COMMIT();
    };

    issue_stage(0, 0);
    if (t < 128) sXsq[t] = g_Xsq[j0 + t];
    else         sXsq[t] = g_Xsq[i0 + (t - 128)];

    for (int c = 0; c < NCHUNK; ++c) {
        const int b = c & 1;
        if (c + 1 < NCHUNK) {
            issue_stage(c + 1, (c + 1) & 1);
            CP_WAIT(1);
        } else {
            CP_WAIT(0);
        }
        __syncthreads();

        const uint32_t st = smb + b * STAGE_B;
        #pragma unroll
        for (int ks = 0; ks < 2; ++ks) {
            const int kb = ks * 32;
            uint32_t Ahi[4][4], Alo[4][4];
            #pragma unroll
            for (int mt = 0; mt < 4; ++mt) {
                uint32_t a = st + (uint32_t)((warpM * 64 + mt * 16 + arow) * 80 + kb + akoff);
                ldsm_x4(Ahi[mt][0], Ahi[mt][1], Ahi[mt][2], Ahi[mt][3], a + 0 * TILE_B);
                ldsm_x4(Alo[mt][0], Alo[mt][1], Alo[mt][2], Alo[mt][3], a + 1 * TILE_B);
            }
            #pragma unroll
            for (int p = 0; p < 2; ++p) {
                uint32_t ba = st + (uint32_t)((warpN * 32 + p * 16 + brow2) * 80 + kb + bko);
                uint32_t Bh[4], Bl[4];
                ldsm_x4(Bh[0], Bh[1], Bh[2], Bh[3], ba + 2 * TILE_B);
                ldsm_x4(Bl[0], Bl[1], Bl[2], Bl[3], ba + 3 * TILE_B);
                #pragma unroll
                for (int mt = 0; mt < 4; ++mt) {
                    mma16816(acc[mt][2 * p],     Ahi[mt], Bh + 0);
                    mma16816(acc[mt][2 * p],     Alo[mt], Bh + 0);
                    mma16816(acc[mt][2 * p],     Ahi[mt], Bl + 0);
                    mma16816(acc[mt][2 * p + 1], Ahi[mt], Bh + 2);
                    mma16816(acc[mt][2 * p + 1], Alo[mt], Bh + 2);
                    mma16816(acc[mt][2 * p + 1], Ahi[mt], Bl + 2);
                }
            }
        }
        __syncthreads();
    }

    // ---- stage dot tile in smem (stride 132: float4-aligned, conflict-free)
    float* stg = reinterpret_cast<float*>(dynsm);      // 128 x 132 floats
    const int gq = lane >> 2, tig = lane & 3;
    #pragma unroll
    for (int nt = 0; nt < 4; ++nt) {
        const int col = warpN * 32 + nt * 8 + tig * 2;
        #pragma unroll
        for (int mt = 0; mt < 4; ++mt) {
            const int r0 = warpM * 64 + mt * 16 + gq;
            float* d = acc[mt][nt];
            stg[r0 * 132 + col]           = d[0];
            stg[r0 * 132 + col + 1]       = d[1];
            stg[(r0 + 8) * 132 + col]     = d[2];
            stg[(r0 + 8) * 132 + col + 1] = d[3];
        }
    }
    __syncthreads();

    // ---- fused per-tile top-10 scan ----
    const bool trans = (t >= 128);
    if (!trans || bi != bj) {
        const int r = t & 127;
        float v[Kn]; int id[Kn];
        #pragma unroll
        for (int k = 0; k < Kn; ++k) { v[k] = 3.4e38f; id[k] = -1; }

        if (!trans) {
            const float4* srow4 = reinterpret_cast<const float4*>(&stg[r * 132]);
            const float4* xsq4  = reinterpret_cast<const float4*>(sXsq);
            const bool diag = (bi == bj);
            #pragma unroll 2
            for (int c4 = 0; c4 < 32; ++c4) {
                float4 dv = srow4[c4];
                float4 xq = xsq4[c4];
                float s0 = xq.x - 2.0f * dv.x;
                float s1 = xq.y - 2.0f * dv.y;
                float s2 = xq.z - 2.0f * dv.z;
                float s3 = xq.w - 2.0f * dv.w;
                int cb = c4 * 4;
                if (diag) {
                    if (cb == r)     s0 = 3.4e38f;
                    if (cb + 1 == r) s1 = 3.4e38f;
                    if (cb + 2 == r) s2 = 3.4e38f;
                    if (cb + 3 == r) s3 = 3.4e38f;
                }
                TOP10_INSERT(s0, j0 + cb,     v, id)
                TOP10_INSERT(s1, j0 + cb + 1, v, id)
                TOP10_INSERT(s2, j0 + cb + 2, v, id)
                TOP10_INSERT(s3, j0 + cb + 3, v, id)
            }
            float2* dst = &g_cand[((size_t)(i0 + r) * NTILE + bj) * Kn];
            #pragma unroll
            for (int k = 0; k < Kn; ++k)
                dst[k] = make_float2(v[k], __int_as_float(id[k]));
        } else {
            #pragma unroll 4
            for (int c = 0; c < 128; ++c) {
                float s = sXsq[128 + c] - 2.0f * stg[c * 132 + r];
                TOP10_INSERT(s, i0 + c, v, id)
            }
            float2* dst = &g_cand[((size_t)(j0 + r) * NTILE + bi) * Kn];
            #pragma unroll
            for (int k = 0; k < Kn; ++k)
                dst[k] = make_float2(v[k], __int_as_float(id[k]));
        }
    }
}

// ---------------- kernel 3: warp-per-row bitonic shuffle merge -------------
// key = (ordered(val) << 32) | idx : smaller d2 first, tie -> smaller idx.
__device__ __forceinline__ uint64_t pack_key(float2 p) {
    uint32_t u = __float_as_uint(p.x);
    u = (u & 0x80000000u) ? ~u : (u | 0x80000000u);
    return ((uint64_t)u << 32) | (uint32_t)__float_as_int(p.y);
}
#define CEX(a, b) { uint64_t _mn = (a) < (b) ? (a) : (b); \
                    uint64_t _mx = (a) < (b) ? (b) : (a); (a) = _mn; (b) = _mx; }
// sort a bitonic 16-sequence ascending (static network)
#define BSORT16(k)                                                             \
    _Pragma("unroll") for (int _d = 8; _d >= 1; _d >>= 1)                      \
        _Pragma("unroll") for (int _i = 0; _i < 16; ++_i)                      \
            if (!(_i & _d)) CEX(k[_i], k[_i + _d])

__global__ void __launch_bounds__(256) topk_merge_kernel() {
    const int lane = threadIdx.x & 31;
    const int row  = blockIdx.x * 8 + (threadIdx.x >> 5);

    // load lists (lane) and (lane+32), each sorted-10 ascending
    uint64_t A[16], K[16];
    {
        const float2* la = &g_cand[((size_t)row * NTILE + lane) * Kn];
        const float2* lb = &g_cand[((size_t)row * NTILE + lane + 32) * Kn];
        uint64_t a[10], b[10];
        #pragma unroll
        for (int k = 0; k < Kn; ++k) { a[k] = pack_key(la[k]); b[k] = pack_key(lb[k]); }
        // bottom-16 of a ∪ b (bitonic first step), then sort
        #pragma unroll
        for (int i = 0; i < 6; ++i)  K[i] = a[i];
        #pragma unroll
        for (int i = 6; i < 10; ++i) K[i] = a[i] < b[15 - i] ? a[i] : b[15 - i];
        #pragma unroll
        for (int i = 10; i < 16; ++i) K[i] = b[15 - i];
        BSORT16(K);
    }

    // 5 butterfly levels: all lanes converge to the global bottom-16
    #pragma unroll
    for (int s = 1; s < 32; s <<= 1) {
        uint64_t O[16];
        #pragma unroll
        for (int i = 0; i < 16; ++i)
            O[i] = __shfl_xor_sync(0xFFFFFFFFu, K[i], s);
        #pragma unroll
        for (int i = 0; i < 16; ++i)
            A[i] = K[i] < O[15 - i] ? K[i] : O[15 - i];
        #pragma unroll
        for (int i = 0; i < 16; ++i) K[i] = A[i];
        BSORT16(K);
    }

    if (lane == 0) {
        #pragma unroll
        for (int k = 0; k < Kn; ++k)
            g_nbr[row * Kn + k] = (int)(uint32_t)(K[k] & 0xffffffffu);
    }
}

// ---------------- kernel 4: per-row loss ----------------------------------
__global__ void __launch_bounds__(320) loss_kernel(const float* __restrict__ X,
                                                   const float* __restrict__ Z) {
    const int i = blockIdx.x;
    const int w = threadIdx.x >> 5;
    const int l = threadIdx.x & 31;
    __shared__ float xd[Kn], zd[Kn];

    int nb = g_nbr[i * Kn + w];
    const float* xi = X + (size_t)i  * Dd;
    const float* xn = X + (size_t)nb * Dd;
    float sx = 0.0f;
    #pragma unroll
    for (int d = 0; d < Dd; d += 32) {
        float df = xi[d + l] - xn[d + l];
        sx = fmaf(df, df, sx);
    }
    const float* zi = Z + (size_t)i  * 64;
    const float* zn = Z + (size_t)nb * 64;
    float sz = 0.0f;
    #pragma unroll
    for (int d = 0; d < 64; d += 32) {
        float df = zi[d + l] - zn[d + l];
        sz = fmaf(df, df, sz);
    }
    #pragma unroll
    for (int o = 16; o > 0; o >>= 1) {
        sx += __shfl_xor_sync(0xFFFFFFFFu, sx, o);
        sz += __shfl_xor_sync(0xFFFFFFFFu, sz, o);
    }
    if (l == 0) { xd[w] = sqrtf(sx); zd[w] = sqrtf(sz); }
    __syncthreads();
    if (threadIdx.x == 0) {
        float xm = 0.0f, zm = 0.0f;
        #pragma unroll
        for (int k = 0; k < Kn; ++k) { xm = fmaxf(xm, xd[k]); zm = fmaxf(zm, zd[k]); }
        xm = fmaxf(xm, 1e-8f);
        zm = fmaxf(zm, 1e-8f);
        float s = 0.0f;
        #pragma unroll
        for (int k = 0; k < Kn; ++k) s += fabsf(xd[k] / xm - zd[k] / zm);
        g_rowsum[i] = s;
    }
}

// ---------------- kernel 5: deterministic final reduction ------------------
__global__ void __launch_bounds__(1024) reduce_kernel(float* __restrict__ out) {
    __shared__ float sm[1024];
    int t = threadIdx.x;
    float s = 0.0f;
    for (int i = t; i < Nn; i += 1024) s += g_rowsum[i];
    sm[t] = s;
    __syncthreads();
    for (int st = 512; st > 0; st >>= 1) {
        if (t < st) sm[t] += sm[t + st];
        __syncthreads();
    }
    if (t == 0) out[0] = sm[0] / (float)(Nn * Kn);
}

// ---------------- launch ---------------------------------------------------
extern "C" void kernel_launch(void* const* d_in, const int* in_sizes, int n_in,
                              void* d_out, int out_size) {
    const float* z = (const float*)d_in[0];
    const float* X = (const float*)d_in[1];
    if (n_in >= 2 && in_sizes[0] != Nn * 64) {
        z = (const float*)d_in[1];
        X = (const float*)d_in[0];
    }
    float* out = (float*)d_out;

    cudaFuncSetAttribute(gemm_mma_kernel, cudaFuncAttributeMaxDynamicSharedMemorySize, SMEM_DYN);

    convert_kernel<<<Nn * 32 / 256, 256>>>(X);
    gemm_mma_kernel<<<NTILE * (NTILE + 1) / 2, 256, SMEM_DYN>>>();
    topk_merge_kernel<<<Nn / 8, 256>>>();
    loss_kernel<<<Nn, 320>>>(X, z);
    reduce_kernel<<<1, 1024>>>(out);
}

// round 10
// speedup vs baseline: 6.2191x; 1.0468x over previous
#include <cuda_runtime.h>
#include <cuda_bf16.h>
#include <cstdint>

#define Nn 8192
#define Dd 256
#define Kn 10
#define NTILE 64                      // Nn / 128

// ---------------- scratch (device globals) ---------------------------------
__device__ float g_Xsq[Nn];
__device__ float2 g_cand[(size_t)Nn * NTILE * Kn];   // 42 MB: [row][tile][10]
__device__ int   g_nbr[Nn * Kn];
__device__ float g_nd2[Nn * Kn];                     // top-10 (Xsq[j]-2dot) per row
__device__ float g_rowsum[Nn];
// K-chunk-major bf16 halves: [chunk c (32 elems)][row][4 x uint4]
__device__ uint4 g_Xhi4[Nn * Dd / 8];
__device__ uint4 g_Xlo4[Nn * Dd / 8];

// ---------------- helpers --------------------------------------------------
__device__ __forceinline__ uint32_t smem_u32(const void* p) {
    uint32_t a;
    asm("{ .reg .u64 t; cvta.to.shared.u64 t, %1; cvt.u32.u64 %0, t; }" : "=r"(a) : "l"(p));
    return a;
}
__device__ __forceinline__ void cp16(uint32_t s, const void* g) {
    asm volatile("cp.async.cg.shared.global [%0], [%1], 16;" :: "r"(s), "l"(g));
}
#define CP_COMMIT() asm volatile("cp.async.commit_group;" ::: "memory")
#define CP_WAIT(n)  asm volatile("cp.async.wait_group %0;" :: "n"(n) : "memory")

__device__ __forceinline__ void ldsm_x4(uint32_t& r0, uint32_t& r1, uint32_t& r2, uint32_t& r3, uint32_t a) {
    asm volatile("ldmatrix.sync.aligned.m8n8.x4.shared.b16 {%0,%1,%2,%3}, [%4];"
                 : "=r"(r0), "=r"(r1), "=r"(r2), "=r"(r3) : "r"(a));
}
__device__ __forceinline__ void mma16816(float* d, const uint32_t* a, const uint32_t* b) {
    asm volatile("mma.sync.aligned.m16n8k16.row.col.f32.bf16.bf16.f32 "
                 "{%0,%1,%2,%3}, {%4,%5,%6,%7}, {%8,%9}, {%0,%1,%2,%3};"
                 : "+f"(d[0]), "+f"(d[1]), "+f"(d[2]), "+f"(d[3])
                 : "r"(a[0]), "r"(a[1]), "r"(a[2]), "r"(a[3]), "r"(b[0]), "r"(b[1]));
}

// register-resident sorted-10 insert (static indices only -> no local mem)
#define TOP10_INSERT(s, j, v, id)                                              \
    if ((s) < v[9]) {                                                          \
        v[9] = (s); id[9] = (j);                                               \
        _Pragma("unroll")                                                      \
        for (int _k = 8; _k >= 0; --_k) {                                      \
            if (v[_k + 1] < v[_k]) {                                           \
                float _tv = v[_k]; v[_k] = v[_k + 1]; v[_k + 1] = _tv;         \
                int _ti = id[_k]; id[_k] = id[_k + 1]; id[_k + 1] = _ti;       \
            }                                                                  \
        }                                                                      \
    }

// ---------------- kernel 0: fp32 -> bf16 hi/lo split + fused Xsq -----------
__global__ void convert_kernel(const float* __restrict__ X) {
    int i = blockIdx.x * 256 + threadIdx.x;    // uint4 index, Nn*32 total
    int lane = threadIdx.x & 31;
    int r = i >> 5;                            // row (one row per warp)
    int q = i & 31;                            // uint4 within row (== lane)
    int c = q >> 2;                            // k-chunk (32 elems)
    int p = q & 3;                             // uint4 within chunk
    const float4* xp = reinterpret_cast<const float4*>(X) + (size_t)i * 2;
    float4 a = xp[0], b = xp[1];
    float v[8] = {a.x, a.y, a.z, a.w, b.x, b.y, b.z, b.w};
    __nv_bfloat16 hi[8], lo[8];
    float s = 0.0f;
    #pragma unroll
    for (int k = 0; k < 8; ++k) {
        s = fmaf(v[k], v[k], s);
        hi[k] = __float2bfloat16(v[k]);
        lo[k] = __float2bfloat16(v[k] - __bfloat162float(hi[k]));
    }
    size_t dst = ((size_t)c * Nn + r) * 4 + p;
    g_Xhi4[dst] = *reinterpret_cast<uint4*>(hi);
    g_Xlo4[dst] = *reinterpret_cast<uint4*>(lo);
    #pragma unroll
    for (int o = 16; o > 0; o >>= 1) s += __shfl_xor_sync(0xFFFFFFFFu, s, o);
    if (lane == 0) g_Xsq[r] = s;
}

// ---------------- kernel 2: symmetric HMMA GEMM + fused per-tile top-10 ----
#define BKc     32
#define NCHUNK  (Dd / BKc)            // 8
#define TILE_B  (128 * 80)
#define STAGE_B (4 * TILE_B)
#define SMEM_DYN (2 * STAGE_B)        // 81920 B (>= 128*132*4 = 67584 stage)

__global__ void __launch_bounds__(256, 2) gemm_mma_kernel() {
    extern __shared__ char dynsm[];
    __shared__ __align__(16) float sXsq[256];
    const uint32_t smb = smem_u32(dynsm);

    const int t = threadIdx.x, wid = t >> 5, lane = t & 31;

    // triangular decode: blockIdx.x -> (bi, bj), bi >= bj
    int tidx = blockIdx.x;
    int bi = (int)((-1.0f + sqrtf(1.0f + 8.0f * (float)tidx)) * 0.5f);
    while ((bi + 1) * (bi + 2) / 2 <= tidx) ++bi;
    while (bi * (bi + 1) / 2 > tidx) --bi;
    int bj = tidx - bi * (bi + 1) / 2;
    const int i0 = bi * 128, j0 = bj * 128;

    const int warpM = wid & 1, warpN = wid >> 1;

    const int lrow = t >> 1, lh = t & 1;

    float acc[4][4][4];
    #pragma unroll
    for (int mt = 0; mt < 4; ++mt)
        #pragma unroll
        for (int nt = 0; nt < 4; ++nt)
            #pragma unroll
            for (int q = 0; q < 4; ++q) acc[mt][nt][q] = 0.0f;

    const int arow = (lane & 15), akoff = (lane >> 4) * 16;
    const int bm = lane >> 3;
    const int brow2 = 8 * (bm >> 1) + (lane & 7);
    const int bko = 16 * (bm & 1);

    auto issue_stage = [&](int c, int b) {
        uint32_t st = smb + b * STAGE_B;
        uint32_t off = (uint32_t)(lrow * 80 + lh * 32);
        size_t cb = (size_t)c * Nn * 4;
        size_t ga = cb + (size_t)(i0 + lrow) * 4 + lh * 2;
        size_t gb = cb + (size_t)(j0 + lrow) * 4 + lh * 2;
        cp16(st + 0 * TILE_B + off,      g_Xhi4 + ga);
        cp16(st + 0 * TILE_B + off + 16, g_Xhi4 + ga + 1);
        cp16(st + 1 * TILE_B + off,      g_Xlo4 + ga);
        cp16(st + 1 * TILE_B + off + 16, g_Xlo4 + ga + 1);
        cp16(st + 2 * TILE_B + off,      g_Xhi4 + gb);
        cp16(st + 2 * TILE_B + off + 16, g_Xhi4 + gb + 1);
        cp16(st + 3 * TILE_B + off,      g_Xlo4 + gb);
        cp16(st + 3 * TILE_B + off + 16, g_Xlo4 + gb + 1);
        CP_COMMIT();
    };

    issue_stage(0, 0);
    if (t < 128) sXsq[t] = g_Xsq[j0 + t];
    else         sXsq[t] = g_Xsq[i0 + (t - 128)];

    for (int c = 0; c < NCHUNK; ++c) {
        const int b = c & 1;
        if (c + 1 < NCHUNK) {
            issue_stage(c + 1, (c + 1) & 1);
            CP_WAIT(1);
        } else {
            CP_WAIT(0);
        }
        __syncthreads();

        const uint32_t st = smb + b * STAGE_B;
        #pragma unroll
        for (int ks = 0; ks < 2; ++ks) {
            const int kb = ks * 32;
            uint32_t Ahi[4][4], Alo[4][4];
            #pragma unroll
            for (int mt = 0; mt < 4; ++mt) {
                uint32_t a = st + (uint32_t)((warpM * 64 + mt * 16 + arow) * 80 + kb + akoff);
                ldsm_x4(Ahi[mt][0], Ahi[mt][1], Ahi[mt][2], Ahi[mt][3], a + 0 * TILE_B);
                ldsm_x4(Alo[mt][0], Alo[mt][1], Alo[mt][2], Alo[mt][3], a + 1 * TILE_B);
            }
            #pragma unroll
            for (int p = 0; p < 2; ++p) {
                uint32_t ba = st + (uint32_t)((warpN * 32 + p * 16 + brow2) * 80 + kb + bko);
                uint32_t Bh[4], Bl[4];
                ldsm_x4(Bh[0], Bh[1], Bh[2], Bh[3], ba + 2 * TILE_B);
                ldsm_x4(Bl[0], Bl[1], Bl[2], Bl[3], ba + 3 * TILE_B);
                #pragma unroll
                for (int mt = 0; mt < 4; ++mt) {
                    mma16816(acc[mt][2 * p],     Ahi[mt], Bh + 0);
                    mma16816(acc[mt][2 * p],     Alo[mt], Bh + 0);
                    mma16816(acc[mt][2 * p],     Ahi[mt], Bl + 0);
                    mma16816(acc[mt][2 * p + 1], Ahi[mt], Bh + 2);
                    mma16816(acc[mt][2 * p + 1], Alo[mt], Bh + 2);
                    mma16816(acc[mt][2 * p + 1], Ahi[mt], Bl + 2);
                }
            }
        }
        __syncthreads();
    }

    // ---- stage dot tile in smem (stride 132: float4-aligned, conflict-free)
    float* stg = reinterpret_cast<float*>(dynsm);      // 128 x 132 floats
    const int gq = lane >> 2, tig = lane & 3;
    #pragma unroll
    for (int nt = 0; nt < 4; ++nt) {
        const int col = warpN * 32 + nt * 8 + tig * 2;
        #pragma unroll
        for (int mt = 0; mt < 4; ++mt) {
            const int r0 = warpM * 64 + mt * 16 + gq;
            float* d = acc[mt][nt];
            stg[r0 * 132 + col]           = d[0];
            stg[r0 * 132 + col + 1]       = d[1];
            stg[(r0 + 8) * 132 + col]     = d[2];
            stg[(r0 + 8) * 132 + col + 1] = d[3];
        }
    }
    __syncthreads();

    // ---- fused per-tile top-10 scan ----
    const bool trans = (t >= 128);
    if (!trans || bi != bj) {
        const int r = t & 127;
        float v[Kn]; int id[Kn];
        #pragma unroll
        for (int k = 0; k < Kn; ++k) { v[k] = 3.4e38f; id[k] = -1; }

        if (!trans) {
            const float4* srow4 = reinterpret_cast<const float4*>(&stg[r * 132]);
            const float4* xsq4  = reinterpret_cast<const float4*>(sXsq);
            const bool diag = (bi == bj);
            #pragma unroll 2
            for (int c4 = 0; c4 < 32; ++c4) {
                float4 dv = srow4[c4];
                float4 xq = xsq4[c4];
                float s0 = xq.x - 2.0f * dv.x;
                float s1 = xq.y - 2.0f * dv.y;
                float s2 = xq.z - 2.0f * dv.z;
                float s3 = xq.w - 2.0f * dv.w;
                int cb = c4 * 4;
                if (diag) {
                    if (cb == r)     s0 = 3.4e38f;
                    if (cb + 1 == r) s1 = 3.4e38f;
                    if (cb + 2 == r) s2 = 3.4e38f;
                    if (cb + 3 == r) s3 = 3.4e38f;
                }
                TOP10_INSERT(s0, j0 + cb,     v, id)
                TOP10_INSERT(s1, j0 + cb + 1, v, id)
                TOP10_INSERT(s2, j0 + cb + 2, v, id)
                TOP10_INSERT(s3, j0 + cb + 3, v, id)
            }
            float2* dst = &g_cand[((size_t)(i0 + r) * NTILE + bj) * Kn];
            #pragma unroll
            for (int k = 0; k < Kn; ++k)
                dst[k] = make_float2(v[k], __int_as_float(id[k]));
        } else {
            #pragma unroll 4
            for (int c = 0; c < 128; ++c) {
                float s = sXsq[128 + c] - 2.0f * stg[c * 132 + r];
                TOP10_INSERT(s, i0 + c, v, id)
            }
            float2* dst = &g_cand[((size_t)(j0 + r) * NTILE + bi) * Kn];
            #pragma unroll
            for (int k = 0; k < Kn; ++k)
                dst[k] = make_float2(v[k], __int_as_float(id[k]));
        }
    }
}

// ---------------- kernel 3: warp-per-row bitonic shuffle merge -------------
// key = (ordered(val) << 32) | idx : smaller d2 first, tie -> smaller idx.
__device__ __forceinline__ uint64_t pack_key(float2 p) {
    uint32_t u = __float_as_uint(p.x);
    u = (u & 0x80000000u) ? ~u : (u | 0x80000000u);
    return ((uint64_t)u << 32) | (uint32_t)__float_as_int(p.y);
}
__device__ __forceinline__ float unpack_val(uint64_t k) {
    uint32_t u = (uint32_t)(k >> 32);
    u = (u & 0x80000000u) ? (u & 0x7fffffffu) : ~u;
    return __uint_as_float(u);
}
#define CEX(a, b) { uint64_t _mn = (a) < (b) ? (a) : (b); \
                    uint64_t _mx = (a) < (b) ? (b) : (a); (a) = _mn; (b) = _mx; }
#define BSORT16(k)                                                             \
    _Pragma("unroll") for (int _d = 8; _d >= 1; _d >>= 1)                      \
        _Pragma("unroll") for (int _i = 0; _i < 16; ++_i)                      \
            if (!(_i & _d)) CEX(k[_i], k[_i + _d])

__global__ void __launch_bounds__(256) topk_merge_kernel() {
    const int lane = threadIdx.x & 31;
    const int row  = blockIdx.x * 8 + (threadIdx.x >> 5);

    uint64_t A[16], K[16];
    {
        const float2* la = &g_cand[((size_t)row * NTILE + lane) * Kn];
        const float2* lb = &g_cand[((size_t)row * NTILE + lane + 32) * Kn];
        uint64_t a[10], b[10];
        #pragma unroll
        for (int k = 0; k < Kn; ++k) { a[k] = pack_key(la[k]); b[k] = pack_key(lb[k]); }
        #pragma unroll
        for (int i = 0; i < 6; ++i)  K[i] = a[i];
        #pragma unroll
        for (int i = 6; i < 10; ++i) K[i] = a[i] < b[15 - i] ? a[i] : b[15 - i];
        #pragma unroll
        for (int i = 10; i < 16; ++i) K[i] = b[15 - i];
        BSORT16(K);
    }

    #pragma unroll
    for (int s = 1; s < 32; s <<= 1) {
        uint64_t O[16];
        #pragma unroll
        for (int i = 0; i < 16; ++i)
            O[i] = __shfl_xor_sync(0xFFFFFFFFu, K[i], s);
        #pragma unroll
        for (int i = 0; i < 16; ++i)
            A[i] = K[i] < O[15 - i] ? K[i] : O[15 - i];
        #pragma unroll
        for (int i = 0; i < 16; ++i) K[i] = A[i];
        BSORT16(K);
    }

    if (lane == 0) {
        #pragma unroll
        for (int k = 0; k < Kn; ++k) {
            g_nbr[row * Kn + k] = (int)(uint32_t)(K[k] & 0xffffffffu);
            g_nd2[row * Kn + k] = unpack_val(K[k]);
        }
    }
}

// ---------------- kernel 4: z-only loss (warp per row) ---------------------
// x_dist comes from the GEMM d2 values: xd = sqrt(max(Xsq[i] + val, 0)).
__global__ void __launch_bounds__(256) loss_kernel(const float* __restrict__ Z) {
    const int lane = threadIdx.x & 31;
    const int row  = blockIdx.x * 8 + (threadIdx.x >> 5);

    const float2 zi = reinterpret_cast<const float2*>(Z + (size_t)row * 64)[lane];
    const float xsq_i = g_Xsq[row];

    float xd[Kn], zd[Kn];
    #pragma unroll
    for (int k = 0; k < Kn; ++k) {
        int nb = g_nbr[row * Kn + k];
        const float2 zn = reinterpret_cast<const float2*>(Z + (size_t)nb * 64)[lane];
        float d0 = zi.x - zn.x, d1 = zi.y - zn.y;
        float sz = fmaf(d0, d0, d1 * d1);
        #pragma unroll
        for (int o = 16; o > 0; o >>= 1) sz += __shfl_xor_sync(0xFFFFFFFFu, sz, o);
        zd[k] = sqrtf(sz);
        xd[k] = sqrtf(fmaxf(xsq_i + g_nd2[row * Kn + k], 0.0f));
    }

    if (lane == 0) {
        float xm = 0.0f, zm = 0.0f;
        #pragma unroll
        for (int k = 0; k < Kn; ++k) { xm = fmaxf(xm, xd[k]); zm = fmaxf(zm, zd[k]); }
        xm = fmaxf(xm, 1e-8f);
        zm = fmaxf(zm, 1e-8f);
        float s = 0.0f;
        #pragma unroll
        for (int k = 0; k < Kn; ++k) s += fabsf(xd[k] / xm - zd[k] / zm);
        g_rowsum[row] = s;
    }
}

// ---------------- kernel 5: deterministic final reduction ------------------
__global__ void __launch_bounds__(1024) reduce_kernel(float* __restrict__ out) {
    __shared__ float sm[1024];
    int t = threadIdx.x;
    float s = 0.0f;
    for (int i = t; i < Nn; i += 1024) s += g_rowsum[i];
    sm[t] = s;
    __syncthreads();
    for (int st = 512; st > 0; st >>= 1) {
        if (t < st) sm[t] += sm[t + st];
        __syncthreads();
    }
    if (t == 0) out[0] = sm[0] / (float)(Nn * Kn);
}

// ---------------- launch ---------------------------------------------------
extern "C" void kernel_launch(void* const* d_in, const int* in_sizes, int n_in,
                              void* d_out, int out_size) {
    const float* z = (const float*)d_in[0];
    const float* X = (const float*)d_in[1];
    if (n_in >= 2 && in_sizes[0] != Nn * 64) {
        z = (const float*)d_in[1];
        X = (const float*)d_in[0];
    }
    float* out = (float*)d_out;

    cudaFuncSetAttribute(gemm_mma_kernel, cudaFuncAttributeMaxDynamicSharedMemorySize, SMEM_DYN);

    convert_kernel<<<Nn * 32 / 256, 256>>>(X);
    gemm_mma_kernel<<<NTILE * (NTILE + 1) / 2, 256, SMEM_DYN>>>();
    topk_merge_kernel<<<Nn / 8, 256>>>();
    loss_kernel<<<Nn / 8, 256>>>(z);
    reduce_kernel<<<1, 1024>>>(out);
}

// round 11
// speedup vs baseline: 6.2700x; 1.0082x over previous
#include <cuda_runtime.h>
#include <cuda_bf16.h>
#include <cstdint>

#define Nn 8192
#define Dd 256
#define Kn 10
#define NTILE 64                      // Nn / 128

// ---------------- scratch (device globals) ---------------------------------
__device__ float g_Xsq[Nn];
__device__ float2 g_cand[(size_t)Nn * NTILE * Kn];   // 42 MB: [row][tile][10]
__device__ float g_rowsum[Nn];
__device__ int   g_done = 0;
// K-chunk-major bf16 halves: [chunk c (32 elems)][row][4 x uint4]
__device__ uint4 g_Xhi4[Nn * Dd / 8];
__device__ uint4 g_Xlo4[Nn * Dd / 8];

// ---------------- helpers --------------------------------------------------
__device__ __forceinline__ uint32_t smem_u32(const void* p) {
    uint32_t a;
    asm("{ .reg .u64 t; cvta.to.shared.u64 t, %1; cvt.u32.u64 %0, t; }" : "=r"(a) : "l"(p));
    return a;
}
__device__ __forceinline__ void cp16(uint32_t s, const void* g) {
    asm volatile("cp.async.cg.shared.global [%0], [%1], 16;" :: "r"(s), "l"(g));
}
#define CP_COMMIT() asm volatile("cp.async.commit_group;" ::: "memory")
#define CP_WAIT(n)  asm volatile("cp.async.wait_group %0;" :: "n"(n) : "memory")

__device__ __forceinline__ void ldsm_x4(uint32_t& r0, uint32_t& r1, uint32_t& r2, uint32_t& r3, uint32_t a) {
    asm volatile("ldmatrix.sync.aligned.m8n8.x4.shared.b16 {%0,%1,%2,%3}, [%4];"
                 : "=r"(r0), "=r"(r1), "=r"(r2), "=r"(r3) : "r"(a));
}
__device__ __forceinline__ void mma16816(float* d, const uint32_t* a, const uint32_t* b) {
    asm volatile("mma.sync.aligned.m16n8k16.row.col.f32.bf16.bf16.f32 "
                 "{%0,%1,%2,%3}, {%4,%5,%6,%7}, {%8,%9}, {%0,%1,%2,%3};"
                 : "+f"(d[0]), "+f"(d[1]), "+f"(d[2]), "+f"(d[3])
                 : "r"(a[0]), "r"(a[1]), "r"(a[2]), "r"(a[3]), "r"(b[0]), "r"(b[1]));
}

// register-resident sorted-10 insert (static indices only -> no local mem)
#define TOP10_INSERT(s, j, v, id)                                              \
    if ((s) < v[9]) {                                                          \
        v[9] = (s); id[9] = (j);                                               \
        _Pragma("unroll")                                                      \
        for (int _k = 8; _k >= 0; --_k) {                                      \
            if (v[_k + 1] < v[_k]) {                                           \
                float _tv = v[_k]; v[_k] = v[_k + 1]; v[_k + 1] = _tv;         \
                int _ti = id[_k]; id[_k] = id[_k + 1]; id[_k + 1] = _ti;       \
            }                                                                  \
        }                                                                      \
    }

// ---------------- kernel 0: fp32 -> bf16 hi/lo split + fused Xsq -----------
__global__ void convert_kernel(const float* __restrict__ X) {
    int i = blockIdx.x * 256 + threadIdx.x;    // uint4 index, Nn*32 total
    int lane = threadIdx.x & 31;
    int r = i >> 5;                            // row (one row per warp)
    int q = i & 31;                            // uint4 within row (== lane)
    int c = q >> 2;                            // k-chunk (32 elems)
    int p = q & 3;                             // uint4 within chunk
    const float4* xp = reinterpret_cast<const float4*>(X) + (size_t)i * 2;
    float4 a = xp[0], b = xp[1];
    float v[8] = {a.x, a.y, a.z, a.w, b.x, b.y, b.z, b.w};
    __nv_bfloat16 hi[8], lo[8];
    float s = 0.0f;
    #pragma unroll
    for (int k = 0; k < 8; ++k) {
        s = fmaf(v[k], v[k], s);
        hi[k] = __float2bfloat16(v[k]);
        lo[k] = __float2bfloat16(v[k] - __bfloat162float(hi[k]));
    }
    size_t dst = ((size_t)c * Nn + r) * 4 + p;
    g_Xhi4[dst] = *reinterpret_cast<uint4*>(hi);
    g_Xlo4[dst] = *reinterpret_cast<uint4*>(lo);
    #pragma unroll
    for (int o = 16; o > 0; o >>= 1) s += __shfl_xor_sync(0xFFFFFFFFu, s, o);
    if (lane == 0) g_Xsq[r] = s;
}

// ---------------- kernel 2: symmetric HMMA GEMM + fused per-tile top-10 ----
#define BKc     32
#define NCHUNK  (Dd / BKc)            // 8
#define TILE_B  (128 * 80)
#define STAGE_B (4 * TILE_B)
#define SMEM_DYN (2 * STAGE_B)        // 81920 B (>= 128*132*4 = 67584 stage)

__global__ void __launch_bounds__(256, 2) gemm_mma_kernel() {
    extern __shared__ char dynsm[];
    __shared__ __align__(16) float sXsq[256];
    const uint32_t smb = smem_u32(dynsm);

    const int t = threadIdx.x, wid = t >> 5, lane = t & 31;

    // triangular decode: blockIdx.x -> (bi, bj), bi >= bj
    int tidx = blockIdx.x;
    int bi = (int)((-1.0f + sqrtf(1.0f + 8.0f * (float)tidx)) * 0.5f);
    while ((bi + 1) * (bi + 2) / 2 <= tidx) ++bi;
    while (bi * (bi + 1) / 2 > tidx) --bi;
    int bj = tidx - bi * (bi + 1) / 2;
    const int i0 = bi * 128, j0 = bj * 128;

    const int warpM = wid & 1, warpN = wid >> 1;

    const int lrow = t >> 1, lh = t & 1;

    float acc[4][4][4];
    #pragma unroll
    for (int mt = 0; mt < 4; ++mt)
        #pragma unroll
        for (int nt = 0; nt < 4; ++nt)
            #pragma unroll
            for (int q = 0; q < 4; ++q) acc[mt][nt][q] = 0.0f;

    const int arow = (lane & 15), akoff = (lane >> 4) * 16;
    const int bm = lane >> 3;
    const int brow2 = 8 * (bm >> 1) + (lane & 7);
    const int bko = 16 * (bm & 1);

    auto issue_stage = [&](int c, int b) {
        uint32_t st = smb + b * STAGE_B;
        uint32_t off = (uint32_t)(lrow * 80 + lh * 32);
        size_t cb = (size_t)c * Nn * 4;
        size_t ga = cb + (size_t)(i0 + lrow) * 4 + lh * 2;
        size_t gb = cb + (size_t)(j0 + lrow) * 4 + lh * 2;
        cp16(st + 0 * TILE_B + off,      g_Xhi4 + ga);
        cp16(st + 0 * TILE_B + off + 16, g_Xhi4 + ga + 1);
        cp16(st + 1 * TILE_B + off,      g_Xlo4 + ga);
        cp16(st + 1 * TILE_B + off + 16, g_Xlo4 + ga + 1);
        cp16(st + 2 * TILE_B + off,      g_Xhi4 + gb);
        cp16(st + 2 * TILE_B + off + 16, g_Xhi4 + gb + 1);
        cp16(st + 3 * TILE_B + off,      g_Xlo4 + gb);
        cp16(st + 3 * TILE_B + off + 16, g_Xlo4 + gb + 1);
        CP_COMMIT();
    };

    issue_stage(0, 0);
    if (t < 128) sXsq[t] = g_Xsq[j0 + t];
    else         sXsq[t] = g_Xsq[i0 + (t - 128)];

    for (int c = 0; c < NCHUNK; ++c) {
        const int b = c & 1;
        if (c + 1 < NCHUNK) {
            issue_stage(c + 1, (c + 1) & 1);
            CP_WAIT(1);
        } else {
            CP_WAIT(0);
        }
        __syncthreads();

        const uint32_t st = smb + b * STAGE_B;
        #pragma unroll
        for (int ks = 0; ks < 2; ++ks) {
            const int kb = ks * 32;
            uint32_t Ahi[4][4], Alo[4][4];
            #pragma unroll
            for (int mt = 0; mt < 4; ++mt) {
                uint32_t a = st + (uint32_t)((warpM * 64 + mt * 16 + arow) * 80 + kb + akoff);
                ldsm_x4(Ahi[mt][0], Ahi[mt][1], Ahi[mt][2], Ahi[mt][3], a + 0 * TILE_B);
                ldsm_x4(Alo[mt][0], Alo[mt][1], Alo[mt][2], Alo[mt][3], a + 1 * TILE_B);
            }
            #pragma unroll
            for (int p = 0; p < 2; ++p) {
                uint32_t ba = st + (uint32_t)((warpN * 32 + p * 16 + brow2) * 80 + kb + bko);
                uint32_t Bh[4], Bl[4];
                ldsm_x4(Bh[0], Bh[1], Bh[2], Bh[3], ba + 2 * TILE_B);
                ldsm_x4(Bl[0], Bl[1], Bl[2], Bl[3], ba + 3 * TILE_B);
                #pragma unroll
                for (int mt = 0; mt < 4; ++mt) {
                    mma16816(acc[mt][2 * p],     Ahi[mt], Bh + 0);
                    mma16816(acc[mt][2 * p],     Alo[mt], Bh + 0);
                    mma16816(acc[mt][2 * p],     Ahi[mt], Bl + 0);
                    mma16816(acc[mt][2 * p + 1], Ahi[mt], Bh + 2);
                    mma16816(acc[mt][2 * p + 1], Alo[mt], Bh + 2);
                    mma16816(acc[mt][2 * p + 1], Ahi[mt], Bl + 2);
                }
            }
        }
        __syncthreads();
    }

    // ---- stage dot tile in smem (stride 132: float4-aligned, conflict-free)
    float* stg = reinterpret_cast<float*>(dynsm);      // 128 x 132 floats
    const int gq = lane >> 2, tig = lane & 3;
    #pragma unroll
    for (int nt = 0; nt < 4; ++nt) {
        const int col = warpN * 32 + nt * 8 + tig * 2;
        #pragma unroll
        for (int mt = 0; mt < 4; ++mt) {
            const int r0 = warpM * 64 + mt * 16 + gq;
            float* d = acc[mt][nt];
            stg[r0 * 132 + col]           = d[0];
            stg[r0 * 132 + col + 1]       = d[1];
            stg[(r0 + 8) * 132 + col]     = d[2];
            stg[(r0 + 8) * 132 + col + 1] = d[3];
        }
    }
    __syncthreads();

    // ---- fused per-tile top-10 scan ----
    const bool trans = (t >= 128);
    if (!trans || bi != bj) {
        const int r = t & 127;
        float v[Kn]; int id[Kn];
        #pragma unroll
        for (int k = 0; k < Kn; ++k) { v[k] = 3.4e38f; id[k] = -1; }

        if (!trans) {
            const float4* srow4 = reinterpret_cast<const float4*>(&stg[r * 132]);
            const float4* xsq4  = reinterpret_cast<const float4*>(sXsq);
            const bool diag = (bi == bj);
            #pragma unroll 2
            for (int c4 = 0; c4 < 32; ++c4) {
                float4 dv = srow4[c4];
                float4 xq = xsq4[c4];
                float s0 = xq.x - 2.0f * dv.x;
                float s1 = xq.y - 2.0f * dv.y;
                float s2 = xq.z - 2.0f * dv.z;
                float s3 = xq.w - 2.0f * dv.w;
                int cb = c4 * 4;
                if (diag) {
                    if (cb == r)     s0 = 3.4e38f;
                    if (cb + 1 == r) s1 = 3.4e38f;
                    if (cb + 2 == r) s2 = 3.4e38f;
                    if (cb + 3 == r) s3 = 3.4e38f;
                }
                TOP10_INSERT(s0, j0 + cb,     v, id)
                TOP10_INSERT(s1, j0 + cb + 1, v, id)
                TOP10_INSERT(s2, j0 + cb + 2, v, id)
                TOP10_INSERT(s3, j0 + cb + 3, v, id)
            }
            float2* dst = &g_cand[((size_t)(i0 + r) * NTILE + bj) * Kn];
            #pragma unroll
            for (int k = 0; k < Kn; ++k)
                dst[k] = make_float2(v[k], __int_as_float(id[k]));
        } else {
            #pragma unroll 4
            for (int c = 0; c < 128; ++c) {
                float s = sXsq[128 + c] - 2.0f * stg[c * 132 + r];
                TOP10_INSERT(s, i0 + c, v, id)
            }
            float2* dst = &g_cand[((size_t)(j0 + r) * NTILE + bi) * Kn];
            #pragma unroll
            for (int k = 0; k < Kn; ++k)
                dst[k] = make_float2(v[k], __int_as_float(id[k]));
        }
    }
}

// ---------------- kernel 3: fused merge + loss + final reduction -----------
// key = (ordered(val) << 32) | idx : smaller d2 first, tie -> smaller idx.
__device__ __forceinline__ uint64_t pack_key(float2 p) {
    uint32_t u = __float_as_uint(p.x);
    u = (u & 0x80000000u) ? ~u : (u | 0x80000000u);
    return ((uint64_t)u << 32) | (uint32_t)__float_as_int(p.y);
}
__device__ __forceinline__ float unpack_val(uint64_t k) {
    uint32_t u = (uint32_t)(k >> 32);
    u = (u & 0x80000000u) ? (u & 0x7fffffffu) : ~u;
    return __uint_as_float(u);
}
#define CEX(a, b) { uint64_t _mn = (a) < (b) ? (a) : (b); \
                    uint64_t _mx = (a) < (b) ? (b) : (a); (a) = _mn; (b) = _mx; }
#define BSORT16(k)                                                             \
    _Pragma("unroll") for (int _d = 8; _d >= 1; _d >>= 1)                      \
        _Pragma("unroll") for (int _i = 0; _i < 16; ++_i)                      \
            if (!(_i & _d)) CEX(k[_i], k[_i + _d])

__global__ void __launch_bounds__(256) topk_loss_kernel(const float* __restrict__ Z,
                                                        float* __restrict__ out) {
    const int lane = threadIdx.x & 31;
    const int row  = blockIdx.x * 8 + (threadIdx.x >> 5);

    // ---- bitonic shuffle merge of 64 sorted-10 lists ----
    uint64_t A[16], K[16];
    {
        const float2* la = &g_cand[((size_t)row * NTILE + lane) * Kn];
        const float2* lb = &g_cand[((size_t)row * NTILE + lane + 32) * Kn];
        uint64_t a[10], b[10];
        #pragma unroll
        for (int k = 0; k < Kn; ++k) { a[k] = pack_key(la[k]); b[k] = pack_key(lb[k]); }
        #pragma unroll
        for (int i = 0; i < 6; ++i)  K[i] = a[i];
        #pragma unroll
        for (int i = 6; i < 10; ++i) K[i] = a[i] < b[15 - i] ? a[i] : b[15 - i];
        #pragma unroll
        for (int i = 10; i < 16; ++i) K[i] = b[15 - i];
        BSORT16(K);
    }
    #pragma unroll
    for (int s = 1; s < 32; s <<= 1) {
        uint64_t O[16];
        #pragma unroll
        for (int i = 0; i < 16; ++i)
            O[i] = __shfl_xor_sync(0xFFFFFFFFu, K[i], s);
        #pragma unroll
        for (int i = 0; i < 16; ++i)
            A[i] = K[i] < O[15 - i] ? K[i] : O[15 - i];
        #pragma unroll
        for (int i = 0; i < 16; ++i) K[i] = A[i];
        BSORT16(K);
    }
    // all lanes now hold the global top-16 keys (we use 10)

    // ---- z distances + loss (x_dist from GEMM d2 values) ----
    const float2 zi = reinterpret_cast<const float2*>(Z + (size_t)row * 64)[lane];
    const float xsq_i = g_Xsq[row];
    float xd[Kn], zd[Kn];
    #pragma unroll
    for (int k = 0; k < Kn; ++k) {
        int nb = (int)(uint32_t)(K[k] & 0xffffffffu);
        const float2 zn = reinterpret_cast<const float2*>(Z + (size_t)nb * 64)[lane];
        float d0 = zi.x - zn.x, d1 = zi.y - zn.y;
        float sz = fmaf(d0, d0, d1 * d1);
        #pragma unroll
        for (int o = 16; o > 0; o >>= 1) sz += __shfl_xor_sync(0xFFFFFFFFu, sz, o);
        zd[k] = sqrtf(sz);
        xd[k] = sqrtf(fmaxf(xsq_i + unpack_val(K[k]), 0.0f));
    }
    if (lane == 0) {
        float xm = 0.0f, zm = 0.0f;
        #pragma unroll
        for (int k = 0; k < Kn; ++k) { xm = fmaxf(xm, xd[k]); zm = fmaxf(zm, zd[k]); }
        xm = fmaxf(xm, 1e-8f);
        zm = fmaxf(zm, 1e-8f);
        float s = 0.0f;
        #pragma unroll
        for (int k = 0; k < Kn; ++k) s += fabsf(xd[k] / xm - zd[k] / zm);
        g_rowsum[row] = s;
    }

    // ---- last-block deterministic final reduction ----
    __shared__ int sflag;
    __syncthreads();
    if (threadIdx.x == 0) {
        __threadfence();
        sflag = (atomicAdd(&g_done, 1) == gridDim.x - 1) ? 1 : 0;
    }
    __syncthreads();
    if (sflag) {
        __threadfence();
        __shared__ float sm[256];
        const int t = threadIdx.x;
        float s = 0.0f;
        for (int i = t; i < Nn; i += 256) s += g_rowsum[i];
        sm[t] = s;
        __syncthreads();
        for (int st = 128; st > 0; st >>= 1) {
            if (t < st) sm[t] += sm[t + st];
            __syncthreads();
        }
        if (t == 0) {
            out[0] = sm[0] / (float)(Nn * Kn);
            g_done = 0;                       // reset for next graph replay
        }
    }
}

// ---------------- launch ---------------------------------------------------
extern "C" void kernel_launch(void* const* d_in, const int* in_sizes, int n_in,
                              void* d_out, int out_size) {
    const float* z = (const float*)d_in[0];
    const float* X = (const float*)d_in[1];
    if (n_in >= 2 && in_sizes[0] != Nn * 64) {
        z = (const float*)d_in[1];
        X = (const float*)d_in[0];
    }
    float* out = (float*)d_out;

    cudaFuncSetAttribute(gemm_mma_kernel, cudaFuncAttributeMaxDynamicSharedMemorySize, SMEM_DYN);

    convert_kernel<<<Nn * 32 / 256, 256>>>(X);
    gemm_mma_kernel<<<NTILE * (NTILE + 1) / 2, 256, SMEM_DYN>>>();
    topk_loss_kernel<<<Nn / 8, 256>>>(z, out);
}

// round 12
// speedup vs baseline: 6.8835x; 1.0978x over previous
#include <cuda_runtime.h>
#include <cuda_bf16.h>
#include <cstdint>

#define Nn 8192
#define Dd 256
#define Kn 10
#define NTILE 64                      // Nn / 128

// ---------------- scratch (device globals) ---------------------------------
__device__ float g_Xsq[Nn];
__device__ float2 g_cand[(size_t)Nn * NTILE * Kn];   // 42 MB: [row][tile][10]
__device__ float g_rowsum[Nn];
__device__ int   g_done = 0;
// K-chunk-major bf16 halves: [chunk c (32 elems)][row][4 x uint4]
__device__ uint4 g_Xhi4[Nn * Dd / 8];
__device__ uint4 g_Xlo4[Nn * Dd / 8];

// ---------------- helpers --------------------------------------------------
__device__ __forceinline__ uint32_t smem_u32(const void* p) {
    uint32_t a;
    asm("{ .reg .u64 t; cvta.to.shared.u64 t, %1; cvt.u32.u64 %0, t; }" : "=r"(a) : "l"(p));
    return a;
}
__device__ __forceinline__ void cp16(uint32_t s, const void* g) {
    asm volatile("cp.async.cg.shared.global [%0], [%1], 16;" :: "r"(s), "l"(g));
}
#define CP_COMMIT() asm volatile("cp.async.commit_group;" ::: "memory")
#define CP_WAIT(n)  asm volatile("cp.async.wait_group %0;" :: "n"(n) : "memory")

__device__ __forceinline__ void ldsm_x4(uint32_t& r0, uint32_t& r1, uint32_t& r2, uint32_t& r3, uint32_t a) {
    asm volatile("ldmatrix.sync.aligned.m8n8.x4.shared.b16 {%0,%1,%2,%3}, [%4];"
                 : "=r"(r0), "=r"(r1), "=r"(r2), "=r"(r3) : "r"(a));
}
__device__ __forceinline__ void mma16816(float* d, const uint32_t* a, const uint32_t* b) {
    asm volatile("mma.sync.aligned.m16n8k16.row.col.f32.bf16.bf16.f32 "
                 "{%0,%1,%2,%3}, {%4,%5,%6,%7}, {%8,%9}, {%0,%1,%2,%3};"
                 : "+f"(d[0]), "+f"(d[1]), "+f"(d[2]), "+f"(d[3])
                 : "r"(a[0]), "r"(a[1]), "r"(a[2]), "r"(a[3]), "r"(b[0]), "r"(b[1]));
}

// register-resident sorted-10 insert (static indices only -> no local mem)
#define TOP10_INSERT(s, j, v, id)                                              \
    if ((s) < v[9]) {                                                          \
        v[9] = (s); id[9] = (j);                                               \
        _Pragma("unroll")                                                      \
        for (int _k = 8; _k >= 0; --_k) {                                      \
            if (v[_k + 1] < v[_k]) {                                           \
                float _tv = v[_k]; v[_k] = v[_k + 1]; v[_k + 1] = _tv;         \
                int _ti = id[_k]; id[_k] = id[_k + 1]; id[_k + 1] = _ti;       \
            }                                                                  \
        }                                                                      \
    }

// 64B-row XOR swizzle: 16B unit u of row r stored at u' = u ^ ((r>>1)&3)
__device__ __forceinline__ uint32_t swz_off(int row, int u) {
    return (uint32_t)(row * 64 + ((u ^ ((row >> 1) & 3)) << 4));
}

// ---------------- kernel 0: fp32 -> bf16 hi/lo split + fused Xsq -----------
__global__ void convert_kernel(const float* __restrict__ X) {
    int i = blockIdx.x * 256 + threadIdx.x;    // uint4 index, Nn*32 total
    int lane = threadIdx.x & 31;
    int r = i >> 5;                            // row (one row per warp)
    int q = i & 31;                            // uint4 within row (== lane)
    int c = q >> 2;                            // k-chunk (32 elems)
    int p = q & 3;                             // uint4 within chunk
    const float4* xp = reinterpret_cast<const float4*>(X) + (size_t)i * 2;
    float4 a = xp[0], b = xp[1];
    float v[8] = {a.x, a.y, a.z, a.w, b.x, b.y, b.z, b.w};
    __nv_bfloat16 hi[8], lo[8];
    float s = 0.0f;
    #pragma unroll
    for (int k = 0; k < 8; ++k) {
        s = fmaf(v[k], v[k], s);
        hi[k] = __float2bfloat16(v[k]);
        lo[k] = __float2bfloat16(v[k] - __bfloat162float(hi[k]));
    }
    size_t dst = ((size_t)c * Nn + r) * 4 + p;
    g_Xhi4[dst] = *reinterpret_cast<uint4*>(hi);
    g_Xlo4[dst] = *reinterpret_cast<uint4*>(lo);
    #pragma unroll
    for (int o = 16; o > 0; o >>= 1) s += __shfl_xor_sync(0xFFFFFFFFu, s, o);
    if (lane == 0) g_Xsq[r] = s;
}

// ---------------- kernel 2: symmetric HMMA GEMM + fused per-tile top-10 ----
#define BKc     32
#define NCHUNK  (Dd / BKc)            // 8
#define TILE_B  (128 * 64)            // 8192 B (64B swizzled rows)
#define STAGE_B (4 * TILE_B)          // 32768: Ahi, Alo, Bhi, Blo
#define SMEM_DYN (3 * STAGE_B)        // 98304 B (>= 128*132*4 = 67584 stage)

__global__ void __launch_bounds__(256, 2) gemm_mma_kernel() {
    extern __shared__ char dynsm[];
    __shared__ __align__(16) float sXsq[256];
    const uint32_t smb = smem_u32(dynsm);

    const int t = threadIdx.x, wid = t >> 5, lane = t & 31;

    // triangular decode: blockIdx.x -> (bi, bj), bi >= bj
    int tidx = blockIdx.x;
    int bi = (int)((-1.0f + sqrtf(1.0f + 8.0f * (float)tidx)) * 0.5f);
    while ((bi + 1) * (bi + 2) / 2 <= tidx) ++bi;
    while (bi * (bi + 1) / 2 > tidx) --bi;
    int bj = tidx - bi * (bi + 1) / 2;
    const int i0 = bi * 128, j0 = bj * 128;

    const int warpM = wid & 1, warpN = wid >> 1;

    const int lrow = t >> 1, lh = t & 1;

    float acc[4][4][4];
    #pragma unroll
    for (int mt = 0; mt < 4; ++mt)
        #pragma unroll
        for (int nt = 0; nt < 4; ++nt)
            #pragma unroll
            for (int q = 0; q < 4; ++q) acc[mt][nt][q] = 0.0f;

    const int arow = (lane & 15), au = (lane >> 4);   // A: rows 0-15, k-unit half
    const int bm = lane >> 3;
    const int brow2 = 8 * (bm >> 1) + (lane & 7);     // B: rows 0-15
    const int bu = (bm & 1);                          // B: k-unit half

    auto issue_stage = [&](int c, int buf) {
        uint32_t st = smb + buf * STAGE_B;
        size_t cb = (size_t)c * Nn * 4;
        size_t ga = cb + (size_t)(i0 + lrow) * 4 + lh * 2;
        size_t gb = cb + (size_t)(j0 + lrow) * 4 + lh * 2;
        #pragma unroll
        for (int q = 0; q < 2; ++q) {
            uint32_t off = swz_off(lrow, lh * 2 + q);
            cp16(st + 0 * TILE_B + off, g_Xhi4 + ga + q);
            cp16(st + 1 * TILE_B + off, g_Xlo4 + ga + q);
            cp16(st + 2 * TILE_B + off, g_Xhi4 + gb + q);
            cp16(st + 3 * TILE_B + off, g_Xlo4 + gb + q);
        }
        CP_COMMIT();
    };

    issue_stage(0, 0);
    issue_stage(1, 1);
    if (t < 128) sXsq[t] = g_Xsq[j0 + t];
    else         sXsq[t] = g_Xsq[i0 + (t - 128)];

    int buf = 0;                       // buffer of chunk c
    for (int c = 0; c < NCHUNK; ++c) {
        if (c + 1 < NCHUNK) { CP_WAIT(1); } else { CP_WAIT(0); }
        __syncthreads();
        // prefetch chunk c+2 into the buffer last read at chunk c-1 (drained)
        if (c + 2 < NCHUNK) {
            int nbuf = buf + 2; if (nbuf >= 3) nbuf -= 3;
            issue_stage(c + 2, nbuf);
        }

        const uint32_t st = smb + buf * STAGE_B;
        #pragma unroll
        for (int ks = 0; ks < 2; ++ks) {
            uint32_t Ahi[4][4], Alo[4][4];
            #pragma unroll
            for (int mt = 0; mt < 4; ++mt) {
                uint32_t a = st + swz_off(warpM * 64 + mt * 16 + arow, ks * 2 + au);
                ldsm_x4(Ahi[mt][0], Ahi[mt][1], Ahi[mt][2], Ahi[mt][3], a + 0 * TILE_B);
                ldsm_x4(Alo[mt][0], Alo[mt][1], Alo[mt][2], Alo[mt][3], a + 1 * TILE_B);
            }
            #pragma unroll
            for (int p = 0; p < 2; ++p) {
                uint32_t ba = st + swz_off(warpN * 32 + p * 16 + brow2, ks * 2 + bu);
                uint32_t Bh[4], Bl[4];
                ldsm_x4(Bh[0], Bh[1], Bh[2], Bh[3], ba + 2 * TILE_B);
                ldsm_x4(Bl[0], Bl[1], Bl[2], Bl[3], ba + 3 * TILE_B);
                #pragma unroll
                for (int mt = 0; mt < 4; ++mt) {
                    mma16816(acc[mt][2 * p],     Ahi[mt], Bh + 0);
                    mma16816(acc[mt][2 * p],     Alo[mt], Bh + 0);
                    mma16816(acc[mt][2 * p],     Ahi[mt], Bl + 0);
                    mma16816(acc[mt][2 * p + 1], Ahi[mt], Bh + 2);
                    mma16816(acc[mt][2 * p + 1], Alo[mt], Bh + 2);
                    mma16816(acc[mt][2 * p + 1], Ahi[mt], Bl + 2);
                }
            }
        }
        if (++buf >= 3) buf -= 3;
    }
    __syncthreads();   // all warps done with smem stages before aliasing as stg

    // ---- stage dot tile in smem (stride 132: float4-aligned, conflict-free)
    float* stg = reinterpret_cast<float*>(dynsm);      // 128 x 132 floats
    const int gq = lane >> 2, tig = lane & 3;
    #pragma unroll
    for (int nt = 0; nt < 4; ++nt) {
        const int col = warpN * 32 + nt * 8 + tig * 2;
        #pragma unroll
        for (int mt = 0; mt < 4; ++mt) {
            const int r0 = warpM * 64 + mt * 16 + gq;
            float* d = acc[mt][nt];
            stg[r0 * 132 + col]           = d[0];
            stg[r0 * 132 + col + 1]       = d[1];
            stg[(r0 + 8) * 132 + col]     = d[2];
            stg[(r0 + 8) * 132 + col + 1] = d[3];
        }
    }
    __syncthreads();

    // ---- fused per-tile top-10 scan ----
    const bool trans = (t >= 128);
    if (!trans || bi != bj) {
        const int r = t & 127;
        float v[Kn]; int id[Kn];
        #pragma unroll
        for (int k = 0; k < Kn; ++k) { v[k] = 3.4e38f; id[k] = -1; }

        if (!trans) {
            const float4* srow4 = reinterpret_cast<const float4*>(&stg[r * 132]);
            const float4* xsq4  = reinterpret_cast<const float4*>(sXsq);
            const bool diag = (bi == bj);
            #pragma unroll 2
            for (int c4 = 0; c4 < 32; ++c4) {
                float4 dv = srow4[c4];
                float4 xq = xsq4[c4];
                float s0 = xq.x - 2.0f * dv.x;
                float s1 = xq.y - 2.0f * dv.y;
                float s2 = xq.z - 2.0f * dv.z;
                float s3 = xq.w - 2.0f * dv.w;
                int cb = c4 * 4;
                if (diag) {
                    if (cb == r)     s0 = 3.4e38f;
                    if (cb + 1 == r) s1 = 3.4e38f;
                    if (cb + 2 == r) s2 = 3.4e38f;
                    if (cb + 3 == r) s3 = 3.4e38f;
                }
                TOP10_INSERT(s0, j0 + cb,     v, id)
                TOP10_INSERT(s1, j0 + cb + 1, v, id)
                TOP10_INSERT(s2, j0 + cb + 2, v, id)
                TOP10_INSERT(s3, j0 + cb + 3, v, id)
            }
            float2* dst = &g_cand[((size_t)(i0 + r) * NTILE + bj) * Kn];
            #pragma unroll
            for (int k = 0; k < Kn; ++k)
                dst[k] = make_float2(v[k], __int_as_float(id[k]));
        } else {
            #pragma unroll 4
            for (int c = 0; c < 128; ++c) {
                float s = sXsq[128 + c] - 2.0f * stg[c * 132 + r];
                TOP10_INSERT(s, i0 + c, v, id)
            }
            float2* dst = &g_cand[((size_t)(j0 + r) * NTILE + bi) * Kn];
            #pragma unroll
            for (int k = 0; k < Kn; ++k)
                dst[k] = make_float2(v[k], __int_as_float(id[k]));
        }
    }
}

// ---------------- kernel 3: fused merge + loss + final reduction -----------
// key = (ordered(val) << 32) | idx : smaller d2 first, tie -> smaller idx.
__device__ __forceinline__ uint64_t pack_key(float2 p) {
    uint32_t u = __float_as_uint(p.x);
    u = (u & 0x80000000u) ? ~u : (u | 0x80000000u);
    return ((uint64_t)u << 32) | (uint32_t)__float_as_int(p.y);
}
__device__ __forceinline__ float unpack_val(uint64_t k) {
    uint32_t u = (uint32_t)(k >> 32);
    u = (u & 0x80000000u) ? (u & 0x7fffffffu) : ~u;
    return __uint_as_float(u);
}
#define CEX(a, b) { uint64_t _mn = (a) < (b) ? (a) : (b); \
                    uint64_t _mx = (a) < (b) ? (b) : (a); (a) = _mn; (b) = _mx; }
#define BSORT16(k)                                                             \
    _Pragma("unroll") for (int _d = 8; _d >= 1; _d >>= 1)                      \
        _Pragma("unroll") for (int _i = 0; _i < 16; ++_i)                      \
            if (!(_i & _d)) CEX(k[_i], k[_i + _d])

__global__ void __launch_bounds__(256) topk_loss_kernel(const float* __restrict__ Z,
                                                        float* __restrict__ out) {
    const int lane = threadIdx.x & 31;
    const int row  = blockIdx.x * 8 + (threadIdx.x >> 5);

    // ---- bitonic shuffle merge of 64 sorted-10 lists ----
    uint64_t A[16], K[16];
    {
        const float2* la = &g_cand[((size_t)row * NTILE + lane) * Kn];
        const float2* lb = &g_cand[((size_t)row * NTILE + lane + 32) * Kn];
        uint64_t a[10], b[10];
        #pragma unroll
        for (int k = 0; k < Kn; ++k) { a[k] = pack_key(la[k]); b[k] = pack_key(lb[k]); }
        #pragma unroll
        for (int i = 0; i < 6; ++i)  K[i] = a[i];
        #pragma unroll
        for (int i = 6; i < 10; ++i) K[i] = a[i] < b[15 - i] ? a[i] : b[15 - i];
        #pragma unroll
        for (int i = 10; i < 16; ++i) K[i] = b[15 - i];
        BSORT16(K);
    }
    #pragma unroll
    for (int s = 1; s < 32; s <<= 1) {
        uint64_t O[16];
        #pragma unroll
        for (int i = 0; i < 16; ++i)
            O[i] = __shfl_xor_sync(0xFFFFFFFFu, K[i], s);
        #pragma unroll
        for (int i = 0; i < 16; ++i)
            A[i] = K[i] < O[15 - i] ? K[i] : O[15 - i];
        #pragma unroll
        for (int i = 0; i < 16; ++i) K[i] = A[i];
        BSORT16(K);
    }
    // all lanes now hold the global top-16 keys (we use 10)

    // ---- z distances + loss (x_dist from GEMM d2 values) ----
    const float2 zi = reinterpret_cast<const float2*>(Z + (size_t)row * 64)[lane];
    const float xsq_i = g_Xsq[row];
    float xd[Kn], zd[Kn];
    #pragma unroll
    for (int k = 0; k < Kn; ++k) {
        int nb = (int)(uint32_t)(K[k] & 0xffffffffu);
        const float2 zn = reinterpret_cast<const float2*>(Z + (size_t)nb * 64)[lane];
        float d0 = zi.x - zn.x, d1 = zi.y - zn.y;
        float sz = fmaf(d0, d0, d1 * d1);
        #pragma unroll
        for (int o = 16; o > 0; o >>= 1) sz += __shfl_xor_sync(0xFFFFFFFFu, sz, o);
        zd[k] = sqrtf(sz);
        xd[k] = sqrtf(fmaxf(xsq_i + unpack_val(K[k]), 0.0f));
    }
    if (lane == 0) {
        float xm = 0.0f, zm = 0.0f;
        #pragma unroll
        for (int k = 0; k < Kn; ++k) { xm = fmaxf(xm, xd[k]); zm = fmaxf(zm, zd[k]); }
        xm = fmaxf(xm, 1e-8f);
        zm = fmaxf(zm, 1e-8f);
        float s = 0.0f;
        #pragma unroll
        for (int k = 0; k < Kn; ++k) s += fabsf(xd[k] / xm - zd[k] / zm);
        g_rowsum[row] = s;
    }

    // ---- last-block deterministic final reduction ----
    __shared__ int sflag;
    __syncthreads();
    if (threadIdx.x == 0) {
        __threadfence();
        sflag = (atomicAdd(&g_done, 1) == gridDim.x - 1) ? 1 : 0;
    }
    __syncthreads();
    if (sflag) {
        __threadfence();
        __shared__ float sm[256];
        const int t = threadIdx.x;
        float s = 0.0f;
        for (int i = t; i < Nn; i += 256) s += g_rowsum[i];
        sm[t] = s;
        __syncthreads();
        for (int st = 128; st > 0; st >>= 1) {
            if (t < st) sm[t] += sm[t + st];
            __syncthreads();
        }
        if (t == 0) {
            out[0] = sm[0] / (float)(Nn * Kn);
            g_done = 0;                       // reset for next graph replay
        }
    }
}

// ---------------- launch ---------------------------------------------------
extern "C" void kernel_launch(void* const* d_in, const int* in_sizes, int n_in,
                              void* d_out, int out_size) {
    const float* z = (const float*)d_in[0];
    const float* X = (const float*)d_in[1];
    if (n_in >= 2 && in_sizes[0] != Nn * 64) {
        z = (const float*)d_in[1];
        X = (const float*)d_in[0];
    }
    float* out = (float*)d_out;

    cudaFuncSetAttribute(gemm_mma_kernel, cudaFuncAttributeMaxDynamicSharedMemorySize, SMEM_DYN);

    convert_kernel<<<Nn * 32 / 256, 256>>>(X);
    gemm_mma_kernel<<<NTILE * (NTILE + 1) / 2, 256, SMEM_DYN>>>();
    topk_loss_kernel<<<Nn / 8, 256>>>(z, out);
}